// round 6
// baseline (speedup 1.0000x reference)
#include <cuda_runtime.h>
#include <cuda_fp16.h>
#include <cuda_fp8.h>
#include <math.h>

#define NN 100000
#define EE 1600000
#define EPAD 1900064          // >= EE + 3*NN, multiple of 4
#define FF 64
#define GG 512
#define CC 10
#define SCALE 16.0f

// ---------------- device scratch ----------------
__device__ __align__(128) unsigned char g_x8[NN * FF];
__device__ __align__(128) unsigned char g_ha[NN * FF];
__device__ __align__(128) unsigned char g_hb[NN * FF];
__device__ float g_dinv[NN];
__device__ float g_degx[NN];      // sum of (ew - 1) per col; zero when all ew==1
__device__ int   g_cnt_e[NN];
__device__ int   g_off[NN];
__device__ int   g_rank[EE];      // within-bucket rank per edge (from k_deg atomic)
__device__ __align__(16) unsigned int g_srt[EPAD];  // row(17b) | coef_fp15(15b)<<17
__device__ int   g_total;
__device__ __align__(16) float g_pool[GG * FF];
__device__ int   g_cnt[GG];

__device__ __forceinline__ void red_add_v4(float* addr, float4 v) {
    asm volatile("red.global.add.v4.f32 [%0], {%1, %2, %3, %4};"
                 :: "l"(addr), "f"(v.x), "f"(v.y), "f"(v.z), "f"(v.w)
                 : "memory");
}

// 16 fp8 (uint4) -> 8 half2
__device__ __forceinline__ void fp8x16_to_h2(uint4 u, __half2* h) {
    const __nv_fp8x2_storage_t* p = reinterpret_cast<const __nv_fp8x2_storage_t*>(&u);
#pragma unroll
    for (int k = 0; k < 8; k++) {
        __half2_raw hr = __nv_cvt_fp8x2_to_halfraw2(p[k], __NV_E4M3);
        h[k] = *reinterpret_cast<__half2*>(&hr);
    }
}
// 16 float -> 16 fp8 (uint4)
__device__ __forceinline__ uint4 f16_to_fp8x16(const float* f) {
    uint4 u;
    __nv_fp8x2_storage_t* p = reinterpret_cast<__nv_fp8x2_storage_t*>(&u);
#pragma unroll
    for (int k = 0; k < 8; k++)
        p[k] = __nv_cvt_float2_to_fp8x2(make_float2(f[2*k], f[2*k+1]), __NV_SATFINITE, __NV_E4M3);
    return u;
}

// ---------------- kernels ----------------

// zero all per-call scratch + convert x -> fp8*SCALE (16 features per thread)
__global__ void k_init(const float* __restrict__ x, int n) {
    int t = blockIdx.x * blockDim.x + threadIdx.x;
    if (t < n * 4) {
        const float4* xp = reinterpret_cast<const float4*>(x) + t * 4;
        float f[16];
#pragma unroll
        for (int k = 0; k < 4; k++) {
            float4 v = __ldg(xp + k);
            f[4*k+0] = v.x * SCALE; f[4*k+1] = v.y * SCALE;
            f[4*k+2] = v.z * SCALE; f[4*k+3] = v.w * SCALE;
        }
        reinterpret_cast<uint4*>(g_x8)[t] = f16_to_fp8x16(f);
    }
    if (t < EPAD / 4) reinterpret_cast<uint4*>(g_srt)[t] = make_uint4(0, 0, 0, 0);
    if (t < n) { g_cnt_e[t] = 0; g_degx[t] = 0.0f; }
    if (t < GG * FF) g_pool[t] = 0.0f;
    if (t < GG) g_cnt[t] = 0;
    if (t == 0) g_total = 0;
}

// in-degree counts; atomic return value = within-bucket rank (stored coalesced).
// float atomic only when ew != 1 (never fires on this input, kept for generality)
__global__ void k_deg(const int* __restrict__ col, const float* __restrict__ ew, int e_total) {
    int e = blockIdx.x * blockDim.x + threadIdx.x;
    if (e >= e_total) return;
    int c = col[e];
    g_rank[e] = atomicAdd(&g_cnt_e[c], 1);
    float w = ew[e];
    if (w != 1.0f) atomicAdd(&g_degx[c], w - 1.0f);
}

// dinv + batch counts + padded exclusive scan (block-local scan + atomic base)
__global__ void k_prep(const int* __restrict__ batch, int n) {
    __shared__ int sh[256];
    __shared__ int base;
    int t = threadIdx.x;
    int i = blockIdx.x * 256 + t;
    int cp = 0;
    if (i < n) {
        int cnt = g_cnt_e[i];
        float deg = 1.0f + (float)cnt + g_degx[i];
        g_dinv[i] = rsqrtf(deg);
        atomicAdd(&g_cnt[batch[i]], 1);
        cp = (cnt + 3) & ~3;            // pad bucket to multiple of 4
    }
    sh[t] = cp; __syncthreads();
    for (int d = 1; d < 256; d <<= 1) {
        int a = (t >= d) ? sh[t - d] : 0;
        __syncthreads();
        sh[t] += a;
        __syncthreads();
    }
    if (t == 255) base = atomicAdd(&g_total, sh[255]);
    __syncthreads();
    if (i < n) g_off[i] = base + sh[t] - cp;
}

// scatter 4B records at precomputed position g_off[col] + rank (no atomics)
__global__ void k_scatter(const int* __restrict__ row, const int* __restrict__ col,
                          const float* __restrict__ ew, int e_total) {
    int e = blockIdx.x * blockDim.x + threadIdx.x;
    if (e >= e_total) return;
    int r = row[e], c = col[e];
    float w = g_dinv[r] * ew[e];
    unsigned short hb = (unsigned short)(__half_as_ushort(__float2half(w)) & 0x7FFF);
    unsigned int u = ((unsigned int)hb << 17) | (unsigned int)r;
    g_srt[__ldg(&g_off[c]) + g_rank[e]] = u;
}

// gather hop: fp8 storage, half2 HFMA2 edge accumulation, fp32 self/combine.
// 4 lanes/node, 16 features per lane (uint4 = 16B gathers). Record loads pipelined.
template<bool POOL>
__global__ __launch_bounds__(256)
void k_hop(const unsigned char* __restrict__ hin, unsigned char* __restrict__ hout,
           const int* __restrict__ batch, int n) {
    int t = blockIdx.x * blockDim.x + threadIdx.x;
    int i = t >> 2, q = t & 3;
    if (i >= n) return;
    const uint4* hin4 = reinterpret_cast<const uint4*>(hin);

    __half2 selfh[8];
    fp8x16_to_h2(__ldg(hin4 + i * 4 + q), selfh);

    __half2 acc[8];
#pragma unroll
    for (int k = 0; k < 8; k++) acc[k] = __float2half2_rn(0.0f);

    int beg4 = g_off[i] >> 2;
    int nq   = (g_cnt_e[i] + 3) >> 2;
    const uint4* srt4 = reinterpret_cast<const uint4*>(g_srt);

    if (nq > 0) {
        uint4 e4 = __ldg(srt4 + beg4);
        for (int j = 0; j < nq; j++) {
            uint4 cur = e4;
            if (j + 1 < nq) e4 = __ldg(srt4 + beg4 + j + 1);   // prefetch next quad
            unsigned int es[4] = { cur.x, cur.y, cur.z, cur.w };
            // issue all 4 gathers before converting/accumulating (max MLP)
            uint4 hv[4];
#pragma unroll
            for (int m = 0; m < 4; m++)
                hv[m] = __ldg(hin4 + (int)(es[m] & 0x1FFFF) * 4 + q);
#pragma unroll
            for (int m = 0; m < 4; m++) {
                __half2 w2 = __half2half2(__ushort_as_half((unsigned short)(es[m] >> 17)));
                const __nv_fp8x2_storage_t* p = reinterpret_cast<const __nv_fp8x2_storage_t*>(&hv[m]);
#pragma unroll
                for (int k = 0; k < 8; k++) {
                    __half2_raw hr = __nv_cvt_fp8x2_to_halfraw2(p[k], __NV_E4M3);
                    acc[k] = __hfma2(w2, *reinterpret_cast<__half2*>(&hr), acc[k]);
                }
            }
        }
    }

    float s = g_dinv[i];
    float s2 = s * s;
    float o[16];
#pragma unroll
    for (int k = 0; k < 8; k++) {
        float2 sf = __half22float2(selfh[k]);
        float2 af = __half22float2(acc[k]);
        o[2*k]   = sf.x * s2 + s * af.x;
        o[2*k+1] = sf.y * s2 + s * af.y;
    }

    if (POOL) {
        int b = batch[i];
        float* base = g_pool + b * FF + q * 16;
#pragma unroll
        for (int k = 0; k < 4; k++)
            red_add_v4(base + 4*k, make_float4(o[4*k], o[4*k+1], o[4*k+2], o[4*k+3]));
    } else {
        reinterpret_cast<uint4*>(hout)[i * 4 + q] = f16_to_fp8x16(o);
    }
}

__global__ void k_head(const float* __restrict__ conv_w, const float* __restrict__ conv_b,
                       const float* __restrict__ lin1_w, const float* __restrict__ lin1_b,
                       const float* __restrict__ lin2_w, const float* __restrict__ lin2_b,
                       float* __restrict__ out) {
    int g = blockIdx.x;
    int f = threadIdx.x;
    __shared__ float sh_t[FF];
    __shared__ float sh_h1[FF];
    __shared__ float sh_h2[FF];
    __shared__ float sh_z[CC];

    float invc = 1.0f / (SCALE * fmaxf((float)g_cnt[g], 1.0f));
    sh_t[f] = g_pool[g * FF + f] * invc;
    __syncthreads();

    float a = conv_b[f];
#pragma unroll
    for (int k = 0; k < FF; k++) a += sh_t[k] * conv_w[k * FF + f];
    sh_h1[f] = a;
    __syncthreads();

    float b = lin1_b[f];
#pragma unroll
    for (int k = 0; k < FF; k++) b += sh_h1[k] * lin1_w[k * FF + f];
    sh_h2[f] = fmaxf(b, 0.0f);
    __syncthreads();

    if (f < CC) {
        float c = lin2_b[f];
#pragma unroll
        for (int k = 0; k < FF; k++) c += sh_h2[k] * lin2_w[k * CC + f];
        sh_z[f] = c;
    }
    __syncthreads();

    if (f < CC) {
        float m = -INFINITY;
#pragma unroll
        for (int j = 0; j < CC; j++) m = fmaxf(m, sh_z[j]);
        float s = 0.0f;
#pragma unroll
        for (int j = 0; j < CC; j++) s += expf(sh_z[j] - m);
        out[g * CC + f] = sh_z[f] - m - logf(s);
    }
}

// ---------------- launch ----------------
extern "C" void kernel_launch(void* const* d_in, const int* in_sizes, int n_in,
                              void* d_out, int out_size) {
    const float* x      = (const float*)d_in[0];
    const int*   ei     = (const int*)d_in[1];
    const float* ew     = (const float*)d_in[2];
    const int*   batch  = (const int*)d_in[3];
    const float* conv_w = (const float*)d_in[4];
    const float* conv_b = (const float*)d_in[5];
    const float* lin1_w = (const float*)d_in[6];
    const float* lin1_b = (const float*)d_in[7];
    const float* lin2_w = (const float*)d_in[8];
    const float* lin2_b = (const float*)d_in[9];
    float* out = (float*)d_out;

    int n = in_sizes[3];
    int e = in_sizes[2];
    const int* row = ei;
    const int* col = ei + e;

    unsigned char *x8, *ha, *hb;
    cudaGetSymbolAddress((void**)&x8, g_x8);
    cudaGetSymbolAddress((void**)&ha, g_ha);
    cudaGetSymbolAddress((void**)&hb, g_hb);

    const int TB = 256;
    int grid_n   = (n + TB - 1) / TB;
    int grid_e   = (e + TB - 1) / TB;
    int init_thr = (EPAD / 4 > n * 4) ? EPAD / 4 : n * 4;
    int grid_i   = (init_thr + TB - 1) / TB;
    int grid_n4  = (n * 4 + TB - 1) / TB;

    k_init<<<grid_i, TB>>>(x, n);
    k_deg<<<grid_e, TB>>>(col, ew, e);
    k_prep<<<grid_n, TB>>>(batch, n);
    k_scatter<<<grid_e, TB>>>(row, col, ew, e);

    k_hop<false><<<grid_n4, TB>>>(x8, ha, batch, n);
    k_hop<false><<<grid_n4, TB>>>(ha, hb, batch, n);
    k_hop<true ><<<grid_n4, TB>>>(hb, (unsigned char*)nullptr, batch, n);

    k_head<<<GG, FF>>>(conv_w, conv_b, lin1_w, lin1_b, lin2_w, lin2_b, out);
}

// round 7
// speedup vs baseline: 1.0408x; 1.0408x over previous
#include <cuda_runtime.h>
#include <cuda_fp16.h>
#include <cuda_fp8.h>
#include <math.h>

#define NN 100000
#define EE 1600000
#define EPAD 1900064          // >= EE + 3*NN, multiple of 4
#define FF 64
#define GG 512
#define CC 10
#define SCALE 16.0f

// ---------------- device scratch ----------------
__device__ __align__(128) unsigned char g_x8[NN * FF];
__device__ __align__(128) unsigned char g_ha[NN * FF];
__device__ __align__(128) unsigned char g_hb[NN * FF];
__device__ float g_dinv[NN];
__device__ float g_degx[NN];
__device__ int   g_cnt_e[NN];
__device__ int   g_off[NN];
__device__ unsigned short g_rank[EE];
__device__ __align__(16) unsigned int g_srt[EPAD];  // row(17b) | coef_fp15(15b)<<17
__device__ int   g_total;
__device__ __align__(16) float g_pool[GG * FF];
__device__ int   g_cnt[GG];

__device__ __forceinline__ void red_add_v4(float* addr, float4 v) {
    asm volatile("red.global.add.v4.f32 [%0], {%1, %2, %3, %4};"
                 :: "l"(addr), "f"(v.x), "f"(v.y), "f"(v.z), "f"(v.w)
                 : "memory");
}

__device__ __forceinline__ void fp8x16_to_h2(uint4 u, __half2* h) {
    const __nv_fp8x2_storage_t* p = reinterpret_cast<const __nv_fp8x2_storage_t*>(&u);
#pragma unroll
    for (int k = 0; k < 8; k++) {
        __half2_raw hr = __nv_cvt_fp8x2_to_halfraw2(p[k], __NV_E4M3);
        h[k] = *reinterpret_cast<__half2*>(&hr);
    }
}
__device__ __forceinline__ uint4 f16_to_fp8x16(const float* f) {
    uint4 u;
    __nv_fp8x2_storage_t* p = reinterpret_cast<__nv_fp8x2_storage_t*>(&u);
#pragma unroll
    for (int k = 0; k < 8; k++)
        p[k] = __nv_cvt_float2_to_fp8x2(make_float2(f[2*k], f[2*k+1]), __NV_SATFINITE, __NV_E4M3);
    return u;
}

// ---------------- kernels ----------------

// zero per-node scratch + convert x -> fp8*SCALE (16 features per thread)
__global__ void k_init(const float* __restrict__ x, int n) {
    int t = blockIdx.x * blockDim.x + threadIdx.x;
    if (t < n * 4) {
        const float4* xp = reinterpret_cast<const float4*>(x) + t * 4;
        float f[16];
#pragma unroll
        for (int k = 0; k < 4; k++) {
            float4 v = __ldg(xp + k);
            f[4*k+0] = v.x * SCALE; f[4*k+1] = v.y * SCALE;
            f[4*k+2] = v.z * SCALE; f[4*k+3] = v.w * SCALE;
        }
        reinterpret_cast<uint4*>(g_x8)[t] = f16_to_fp8x16(f);
    }
    if (t < n) { g_cnt_e[t] = 0; g_degx[t] = 0.0f; }
    if (t < GG * FF) g_pool[t] = 0.0f;
    if (t < GG) g_cnt[t] = 0;
    if (t == 0) g_total = 0;
}

// in-degree counts; atomic return = within-bucket rank (stored coalesced, u16)
__global__ void k_deg(const int* __restrict__ col, const float* __restrict__ ew, int e_total) {
    int e = blockIdx.x * blockDim.x + threadIdx.x;
    if (e >= e_total) return;
    int c = col[e];
    g_rank[e] = (unsigned short)atomicAdd(&g_cnt_e[c], 1);
    float w = ew[e];
    if (w != 1.0f) atomicAdd(&g_degx[c], w - 1.0f);
}

// dinv + batch counts + padded exclusive scan; zero the <=3 pad slots per bucket
__global__ void k_prep(const int* __restrict__ batch, int n) {
    __shared__ int sh[256];
    __shared__ int base;
    int t = threadIdx.x;
    int i = blockIdx.x * 256 + t;
    int cnt = 0, cp = 0;
    if (i < n) {
        cnt = g_cnt_e[i];
        float deg = 1.0f + (float)cnt + g_degx[i];
        g_dinv[i] = rsqrtf(deg);
        atomicAdd(&g_cnt[batch[i]], 1);
        cp = (cnt + 3) & ~3;
    }
    sh[t] = cp; __syncthreads();
    for (int d = 1; d < 256; d <<= 1) {
        int a = (t >= d) ? sh[t - d] : 0;
        __syncthreads();
        sh[t] += a;
        __syncthreads();
    }
    if (t == 255) base = atomicAdd(&g_total, sh[255]);
    __syncthreads();
    if (i < n) {
        int off = base + sh[t] - cp;
        g_off[i] = off;
        for (int z = cnt; z < cp; z++) g_srt[off + z] = 0u;   // zero pad slots only
    }
}

// scatter 4B records at g_off[col] + rank (no atomics)
__global__ void k_scatter(const int* __restrict__ row, const int* __restrict__ col,
                          const float* __restrict__ ew, int e_total) {
    int e = blockIdx.x * blockDim.x + threadIdx.x;
    if (e >= e_total) return;
    int r = row[e], c = col[e];
    float w = g_dinv[r] * ew[e];
    unsigned short hb = (unsigned short)(__half_as_ushort(__float2half(w)) & 0x7FFF);
    unsigned int u = ((unsigned int)hb << 17) | (unsigned int)r;
    g_srt[__ldg(&g_off[c]) + (int)g_rank[e]] = u;
}

// gather hop: fp8 storage, half2 HFMA2 accumulation. 4 lanes/node, 16 features/lane.
template<bool POOL>
__global__ __launch_bounds__(256)
void k_hop(const unsigned char* __restrict__ hin, unsigned char* __restrict__ hout,
           const int* __restrict__ batch, int n) {
    int t = blockIdx.x * blockDim.x + threadIdx.x;
    int i = t >> 2, q = t & 3;
    if (i >= n) return;
    const uint4* hin4 = reinterpret_cast<const uint4*>(hin);

    __half2 selfh[8];
    fp8x16_to_h2(__ldg(hin4 + i * 4 + q), selfh);

    __half2 acc[8];
#pragma unroll
    for (int k = 0; k < 8; k++) acc[k] = __float2half2_rn(0.0f);

    int beg4 = g_off[i] >> 2;
    int nq   = (g_cnt_e[i] + 3) >> 2;
    const uint4* srt4 = reinterpret_cast<const uint4*>(g_srt);

    for (int j = 0; j < nq; j++) {
        uint4 e4 = __ldg(srt4 + beg4 + j);
        unsigned int es[4] = { e4.x, e4.y, e4.z, e4.w };
#pragma unroll
        for (int m = 0; m < 4; m++) {
            unsigned int u = es[m];
            int r = (int)(u & 0x1FFFF);
            __half2 w2 = __half2half2(__ushort_as_half((unsigned short)(u >> 17)));
            uint4 hv = __ldg(hin4 + r * 4 + q);
            const __nv_fp8x2_storage_t* p = reinterpret_cast<const __nv_fp8x2_storage_t*>(&hv);
#pragma unroll
            for (int k = 0; k < 8; k++) {
                __half2_raw hr = __nv_cvt_fp8x2_to_halfraw2(p[k], __NV_E4M3);
                acc[k] = __hfma2(w2, *reinterpret_cast<__half2*>(&hr), acc[k]);
            }
        }
    }

    float s = g_dinv[i];
    float s2 = s * s;
    float o[16];
#pragma unroll
    for (int k = 0; k < 8; k++) {
        float2 sf = __half22float2(selfh[k]);
        float2 af = __half22float2(acc[k]);
        o[2*k]   = sf.x * s2 + s * af.x;
        o[2*k+1] = sf.y * s2 + s * af.y;
    }

    if (POOL) {
        int b = batch[i];
        float* base = g_pool + b * FF + q * 16;
#pragma unroll
        for (int k = 0; k < 4; k++)
            red_add_v4(base + 4*k, make_float4(o[4*k], o[4*k+1], o[4*k+2], o[4*k+3]));
    } else {
        reinterpret_cast<uint4*>(hout)[i * 4 + q] = f16_to_fp8x16(o);
    }
}

__global__ void k_head(const float* __restrict__ conv_w, const float* __restrict__ conv_b,
                       const float* __restrict__ lin1_w, const float* __restrict__ lin1_b,
                       const float* __restrict__ lin2_w, const float* __restrict__ lin2_b,
                       float* __restrict__ out) {
    int g = blockIdx.x;
    int f = threadIdx.x;
    __shared__ float sh_t[FF];
    __shared__ float sh_h1[FF];
    __shared__ float sh_h2[FF];
    __shared__ float sh_z[CC];

    float invc = 1.0f / (SCALE * fmaxf((float)g_cnt[g], 1.0f));
    sh_t[f] = g_pool[g * FF + f] * invc;
    __syncthreads();

    float a = conv_b[f];
#pragma unroll
    for (int k = 0; k < FF; k++) a += sh_t[k] * conv_w[k * FF + f];
    sh_h1[f] = a;
    __syncthreads();

    float b = lin1_b[f];
#pragma unroll
    for (int k = 0; k < FF; k++) b += sh_h1[k] * lin1_w[k * FF + f];
    sh_h2[f] = fmaxf(b, 0.0f);
    __syncthreads();

    if (f < CC) {
        float c = lin2_b[f];
#pragma unroll
        for (int k = 0; k < FF; k++) c += sh_h2[k] * lin2_w[k * CC + f];
        sh_z[f] = c;
    }
    __syncthreads();

    if (f < CC) {
        float m = -INFINITY;
#pragma unroll
        for (int j = 0; j < CC; j++) m = fmaxf(m, sh_z[j]);
        float s = 0.0f;
#pragma unroll
        for (int j = 0; j < CC; j++) s += expf(sh_z[j] - m);
        out[g * CC + f] = sh_z[f] - m - logf(s);
    }
}

// ---------------- launch ----------------
extern "C" void kernel_launch(void* const* d_in, const int* in_sizes, int n_in,
                              void* d_out, int out_size) {
    const float* x      = (const float*)d_in[0];
    const int*   ei     = (const int*)d_in[1];
    const float* ew     = (const float*)d_in[2];
    const int*   batch  = (const int*)d_in[3];
    const float* conv_w = (const float*)d_in[4];
    const float* conv_b = (const float*)d_in[5];
    const float* lin1_w = (const float*)d_in[6];
    const float* lin1_b = (const float*)d_in[7];
    const float* lin2_w = (const float*)d_in[8];
    const float* lin2_b = (const float*)d_in[9];
    float* out = (float*)d_out;

    int n = in_sizes[3];
    int e = in_sizes[2];
    const int* row = ei;
    const int* col = ei + e;

    unsigned char *x8, *ha, *hb;
    cudaGetSymbolAddress((void**)&x8, g_x8);
    cudaGetSymbolAddress((void**)&ha, g_ha);
    cudaGetSymbolAddress((void**)&hb, g_hb);

    const int TB = 256;
    int grid_n  = (n + TB - 1) / TB;
    int grid_e  = (e + TB - 1) / TB;
    int grid_n4 = (n * 4 + TB - 1) / TB;

    k_init<<<grid_n4, TB>>>(x, n);
    k_deg<<<grid_e, TB>>>(col, ew, e);
    k_prep<<<grid_n, TB>>>(batch, n);
    k_scatter<<<grid_e, TB>>>(row, col, ew, e);

    k_hop<false><<<grid_n4, TB>>>(x8, ha, batch, n);
    k_hop<false><<<grid_n4, TB>>>(ha, hb, batch, n);
    k_hop<true ><<<grid_n4, TB>>>(hb, (unsigned char*)nullptr, batch, n);

    k_head<<<GG, FF>>>(conv_w, conv_b, lin1_w, lin1_b, lin2_w, lin2_b, out);
}

// round 8
// speedup vs baseline: 1.0515x; 1.0104x over previous
#include <cuda_runtime.h>
#include <cuda_fp16.h>
#include <cuda_fp8.h>
#include <math.h>

#define NN 100000
#define EE 1600000
#define EPAD 1900064
#define FF 64
#define GG 512
#define CC 10
#define SCALE 16.0f

// ---------------- device scratch ----------------
__device__ __align__(128) unsigned char g_x8[NN * FF];
__device__ __align__(128) unsigned char g_ha[NN * FF];
__device__ __align__(128) unsigned char g_hb[NN * FF];
__device__ float g_dinv[NN];
__device__ float g_degx[NN];
__device__ int   g_cnt_e[NN];
__device__ __align__(8) int2 g_offcnt[NN];   // (bucket offset, count)
__device__ unsigned short g_rank[EE];
__device__ __align__(16) unsigned int g_srt[EPAD];  // row(17b) | coef_fp15(15b)<<17
__device__ int   g_total;
__device__ __align__(16) float g_pool[GG * FF];
__device__ int   g_cnt[GG];

__device__ __forceinline__ void red_add_v4(float* addr, float4 v) {
    asm volatile("red.global.add.v4.f32 [%0], {%1, %2, %3, %4};"
                 :: "l"(addr), "f"(v.x), "f"(v.y), "f"(v.z), "f"(v.w)
                 : "memory");
}

__device__ __forceinline__ void fp8x16_to_h2(uint4 u, __half2* h) {
    const __nv_fp8x2_storage_t* p = reinterpret_cast<const __nv_fp8x2_storage_t*>(&u);
#pragma unroll
    for (int k = 0; k < 8; k++) {
        __half2_raw hr = __nv_cvt_fp8x2_to_halfraw2(p[k], __NV_E4M3);
        h[k] = *reinterpret_cast<__half2*>(&hr);
    }
}
__device__ __forceinline__ uint4 f16_to_fp8x16(const float* f) {
    uint4 u;
    __nv_fp8x2_storage_t* p = reinterpret_cast<__nv_fp8x2_storage_t*>(&u);
#pragma unroll
    for (int k = 0; k < 8; k++)
        p[k] = __nv_cvt_float2_to_fp8x2(make_float2(f[2*k], f[2*k+1]), __NV_SATFINITE, __NV_E4M3);
    return u;
}

// ---------------- kernels ----------------

__global__ void k_init(const float* __restrict__ x, int n) {
    int t = blockIdx.x * blockDim.x + threadIdx.x;
    if (t < n * 4) {
        const float4* xp = reinterpret_cast<const float4*>(x) + t * 4;
        float f[16];
#pragma unroll
        for (int k = 0; k < 4; k++) {
            float4 v = __ldg(xp + k);
            f[4*k+0] = v.x * SCALE; f[4*k+1] = v.y * SCALE;
            f[4*k+2] = v.z * SCALE; f[4*k+3] = v.w * SCALE;
        }
        reinterpret_cast<uint4*>(g_x8)[t] = f16_to_fp8x16(f);
    }
    if (t < n) { g_cnt_e[t] = 0; g_degx[t] = 0.0f; }
    if (t < GG * FF) g_pool[t] = 0.0f;
    if (t < GG) g_cnt[t] = 0;
    if (t == 0) g_total = 0;
}

__global__ void k_deg(const int* __restrict__ col, const float* __restrict__ ew, int e_total) {
    int e = blockIdx.x * blockDim.x + threadIdx.x;
    if (e >= e_total) return;
    int c = col[e];
    g_rank[e] = (unsigned short)atomicAdd(&g_cnt_e[c], 1);
    float w = ew[e];
    if (w != 1.0f) atomicAdd(&g_degx[c], w - 1.0f);
}

__global__ void k_prep(const int* __restrict__ batch, int n) {
    __shared__ int sh[256];
    __shared__ int base;
    int t = threadIdx.x;
    int i = blockIdx.x * 256 + t;
    int cnt = 0, cp = 0;
    if (i < n) {
        cnt = g_cnt_e[i];
        float deg = 1.0f + (float)cnt + g_degx[i];
        g_dinv[i] = rsqrtf(deg);
        atomicAdd(&g_cnt[batch[i]], 1);
        cp = (cnt + 3) & ~3;
    }
    sh[t] = cp; __syncthreads();
    for (int d = 1; d < 256; d <<= 1) {
        int a = (t >= d) ? sh[t - d] : 0;
        __syncthreads();
        sh[t] += a;
        __syncthreads();
    }
    if (t == 255) base = atomicAdd(&g_total, sh[255]);
    __syncthreads();
    if (i < n) {
        int off = base + sh[t] - cp;
        g_offcnt[i] = make_int2(off, cnt);
        for (int z = cnt; z < cp; z++) g_srt[off + z] = 0u;
    }
}

__global__ void k_scatter(const int* __restrict__ row, const int* __restrict__ col,
                          const float* __restrict__ ew, int e_total) {
    int e = blockIdx.x * blockDim.x + threadIdx.x;
    if (e >= e_total) return;
    int r = row[e], c = col[e];
    float w = g_dinv[r] * ew[e];
    unsigned short hb = (unsigned short)(__half_as_ushort(__float2half(w)) & 0x7FFF);
    unsigned int u = ((unsigned int)hb << 17) | (unsigned int)r;
    g_srt[__ldg(&g_offcnt[c].x) + (int)g_rank[e]] = u;
}

// gather hop: fp8 storage, half2 HFMA2 accumulation, record-quad double buffered.
template<bool POOL>
__global__ __launch_bounds__(256)
void k_hop(const unsigned char* __restrict__ hin, unsigned char* __restrict__ hout,
           const int* __restrict__ batch, int n) {
    int t = blockIdx.x * blockDim.x + threadIdx.x;
    int i = t >> 2, q = t & 3;
    if (i >= n) return;
    const uint4* hin4 = reinterpret_cast<const uint4*>(hin);

    __half2 selfh[8];
    fp8x16_to_h2(__ldg(hin4 + i * 4 + q), selfh);

    __half2 acc[8];
#pragma unroll
    for (int k = 0; k < 8; k++) acc[k] = __float2half2_rn(0.0f);

    int2 oc = __ldg(&g_offcnt[i]);
    int beg4 = oc.x >> 2;
    int nq   = (oc.y + 3) >> 2;
    const uint4* srt4 = reinterpret_cast<const uint4*>(g_srt);

    if (nq > 0) {
        uint4 e4 = __ldg(srt4 + beg4);                 // first record quad
        for (int j = 0; j < nq; j++) {
            unsigned int es[4] = { e4.x, e4.y, e4.z, e4.w };
            if (j + 1 < nq) e4 = __ldg(srt4 + beg4 + j + 1);   // overlap next record load
#pragma unroll
            for (int m = 0; m < 4; m++) {
                unsigned int u = es[m];
                int r = (int)(u & 0x1FFFF);
                __half2 w2 = __half2half2(__ushort_as_half((unsigned short)(u >> 17)));
                uint4 hv = __ldg(hin4 + r * 4 + q);
                const __nv_fp8x2_storage_t* p = reinterpret_cast<const __nv_fp8x2_storage_t*>(&hv);
#pragma unroll
                for (int k = 0; k < 8; k++) {
                    __half2_raw hr = __nv_cvt_fp8x2_to_halfraw2(p[k], __NV_E4M3);
                    acc[k] = __hfma2(w2, *reinterpret_cast<__half2*>(&hr), acc[k]);
                }
            }
        }
    }

    float s = g_dinv[i];
    float s2 = s * s;
    float o[16];
#pragma unroll
    for (int k = 0; k < 8; k++) {
        float2 sf = __half22float2(selfh[k]);
        float2 af = __half22float2(acc[k]);
        o[2*k]   = sf.x * s2 + s * af.x;
        o[2*k+1] = sf.y * s2 + s * af.y;
    }

    if (POOL) {
        int b = batch[i];
        float* base = g_pool + b * FF + q * 16;
#pragma unroll
        for (int k = 0; k < 4; k++)
            red_add_v4(base + 4*k, make_float4(o[4*k], o[4*k+1], o[4*k+2], o[4*k+3]));
    } else {
        reinterpret_cast<uint4*>(hout)[i * 4 + q] = f16_to_fp8x16(o);
    }
}

__global__ void k_head(const float* __restrict__ conv_w, const float* __restrict__ conv_b,
                       const float* __restrict__ lin1_w, const float* __restrict__ lin1_b,
                       const float* __restrict__ lin2_w, const float* __restrict__ lin2_b,
                       float* __restrict__ out) {
    int g = blockIdx.x;
    int f = threadIdx.x;
    __shared__ float sh_t[FF];
    __shared__ float sh_h1[FF];
    __shared__ float sh_h2[FF];
    __shared__ float sh_z[CC];

    float invc = 1.0f / (SCALE * fmaxf((float)g_cnt[g], 1.0f));
    sh_t[f] = g_pool[g * FF + f] * invc;
    __syncthreads();

    float a = conv_b[f];
#pragma unroll
    for (int k = 0; k < FF; k++) a += sh_t[k] * conv_w[k * FF + f];
    sh_h1[f] = a;
    __syncthreads();

    float b = lin1_b[f];
#pragma unroll
    for (int k = 0; k < FF; k++) b += sh_h1[k] * lin1_w[k * FF + f];
    sh_h2[f] = fmaxf(b, 0.0f);
    __syncthreads();

    if (f < CC) {
        float c = lin2_b[f];
#pragma unroll
        for (int k = 0; k < FF; k++) c += sh_h2[k] * lin2_w[k * CC + f];
        sh_z[f] = c;
    }
    __syncthreads();

    if (f < CC) {
        float m = -INFINITY;
#pragma unroll
        for (int j = 0; j < CC; j++) m = fmaxf(m, sh_z[j]);
        float s = 0.0f;
#pragma unroll
        for (int j = 0; j < CC; j++) s += expf(sh_z[j] - m);
        out[g * CC + f] = sh_z[f] - m - logf(s);
    }
}

// ---------------- launch ----------------
extern "C" void kernel_launch(void* const* d_in, const int* in_sizes, int n_in,
                              void* d_out, int out_size) {
    const float* x      = (const float*)d_in[0];
    const int*   ei     = (const int*)d_in[1];
    const float* ew     = (const float*)d_in[2];
    const int*   batch  = (const int*)d_in[3];
    const float* conv_w = (const float*)d_in[4];
    const float* conv_b = (const float*)d_in[5];
    const float* lin1_w = (const float*)d_in[6];
    const float* lin1_b = (const float*)d_in[7];
    const float* lin2_w = (const float*)d_in[8];
    const float* lin2_b = (const float*)d_in[9];
    float* out = (float*)d_out;

    int n = in_sizes[3];
    int e = in_sizes[2];
    const int* row = ei;
    const int* col = ei + e;

    unsigned char *x8, *ha, *hb;
    cudaGetSymbolAddress((void**)&x8, g_x8);
    cudaGetSymbolAddress((void**)&ha, g_ha);
    cudaGetSymbolAddress((void**)&hb, g_hb);

    const int TB = 256;
    int grid_n  = (n + TB - 1) / TB;
    int grid_e  = (e + TB - 1) / TB;
    int grid_n4 = (n * 4 + TB - 1) / TB;

    k_init<<<grid_n4, TB>>>(x, n);
    k_deg<<<grid_e, TB>>>(col, ew, e);
    k_prep<<<grid_n, TB>>>(batch, n);
    k_scatter<<<grid_e, TB>>>(row, col, ew, e);

    k_hop<false><<<grid_n4, TB>>>(x8, ha, batch, n);
    k_hop<false><<<grid_n4, TB>>>(ha, hb, batch, n);
    k_hop<true ><<<grid_n4, TB>>>(hb, (unsigned char*)nullptr, batch, n);

    k_head<<<GG, FF>>>(conv_w, conv_b, lin1_w, lin1_b, lin2_w, lin2_b, out);
}

// round 9
// speedup vs baseline: 1.0708x; 1.0183x over previous
#include <cuda_runtime.h>
#include <cuda_fp16.h>
#include <cuda_fp8.h>
#include <math.h>

#define NN 100000
#define EE 1600000
#define EPAD 1900064
#define FF 64
#define GG 512
#define CC 10
#define SCALE 16.0f

// ---------------- device scratch (zero-initialized at load; every call restores) ----
__device__ __align__(128) unsigned char g_x8[NN * FF];
__device__ __align__(128) unsigned char g_ha[NN * FF];
__device__ __align__(128) unsigned char g_hb[NN * FF];
__device__ float g_dinv[NN];
__device__ float g_degx[NN];            // zeroed by k_prep after read
__device__ int   g_cnt_e[NN];           // zeroed by k_prep after read
__device__ __align__(8) int2 g_offcnt[NN];
__device__ __align__(8) unsigned short g_rank[EE];
__device__ __align__(16) unsigned int g_srt[EPAD];
__device__ int   g_total;               // zeroed by k_head
__device__ __align__(16) float g_pool[GG * FF];   // zeroed by k_head after read
__device__ int   g_cnt[GG];             // zeroed by k_head after read

__device__ __forceinline__ void red_add_v4(float* addr, float4 v) {
    asm volatile("red.global.add.v4.f32 [%0], {%1, %2, %3, %4};"
                 :: "l"(addr), "f"(v.x), "f"(v.y), "f"(v.z), "f"(v.w)
                 : "memory");
}

__device__ __forceinline__ void fp8x16_to_h2(uint4 u, __half2* h) {
    const __nv_fp8x2_storage_t* p = reinterpret_cast<const __nv_fp8x2_storage_t*>(&u);
#pragma unroll
    for (int k = 0; k < 8; k++) {
        __half2_raw hr = __nv_cvt_fp8x2_to_halfraw2(p[k], __NV_E4M3);
        h[k] = *reinterpret_cast<__half2*>(&hr);
    }
}
__device__ __forceinline__ uint4 f16_to_fp8x16(const float* f) {
    uint4 u;
    __nv_fp8x2_storage_t* p = reinterpret_cast<__nv_fp8x2_storage_t*>(&u);
#pragma unroll
    for (int k = 0; k < 8; k++)
        p[k] = __nv_cvt_float2_to_fp8x2(make_float2(f[2*k], f[2*k+1]), __NV_SATFINITE, __NV_E4M3);
    return u;
}

// ---------------- kernels ----------------

// fused: x -> fp8*SCALE conversion (t < n*4) + 4-edge-batched degree/rank (4t < e)
__global__ void k_cvt_deg(const float* __restrict__ x,
                          const int* __restrict__ col, const float* __restrict__ ew,
                          int n, int e) {
    int t = blockIdx.x * blockDim.x + threadIdx.x;
    if (t < n * 4) {
        const float4* xp = reinterpret_cast<const float4*>(x) + t * 4;
        float f[16];
#pragma unroll
        for (int k = 0; k < 4; k++) {
            float4 v = __ldg(xp + k);
            f[4*k+0] = v.x * SCALE; f[4*k+1] = v.y * SCALE;
            f[4*k+2] = v.z * SCALE; f[4*k+3] = v.w * SCALE;
        }
        reinterpret_cast<uint4*>(g_x8)[t] = f16_to_fp8x16(f);
    }
    int base = t * 4;
    if ((e & 3) == 0) {                       // vector path (e multiple of 4)
        if (base < e) {
            int4   c4 = __ldg(reinterpret_cast<const int4*>(col) + t);
            float4 w4 = __ldg(reinterpret_cast<const float4*>(ew) + t);
            ushort4 rk;
            rk.x = (unsigned short)atomicAdd(&g_cnt_e[c4.x], 1);
            rk.y = (unsigned short)atomicAdd(&g_cnt_e[c4.y], 1);
            rk.z = (unsigned short)atomicAdd(&g_cnt_e[c4.z], 1);
            rk.w = (unsigned short)atomicAdd(&g_cnt_e[c4.w], 1);
            if (w4.x != 1.0f) atomicAdd(&g_degx[c4.x], w4.x - 1.0f);
            if (w4.y != 1.0f) atomicAdd(&g_degx[c4.y], w4.y - 1.0f);
            if (w4.z != 1.0f) atomicAdd(&g_degx[c4.z], w4.z - 1.0f);
            if (w4.w != 1.0f) atomicAdd(&g_degx[c4.w], w4.w - 1.0f);
            reinterpret_cast<ushort4*>(g_rank)[t] = rk;
        }
    } else {
        for (int m = 0; m < 4; m++) {
            int ei_ = base + m;
            if (ei_ < e) {
                int c = col[ei_];
                g_rank[ei_] = (unsigned short)atomicAdd(&g_cnt_e[c], 1);
                float w = ew[ei_];
                if (w != 1.0f) atomicAdd(&g_degx[c], w - 1.0f);
            }
        }
    }
}

// dinv + batch counts + padded exclusive scan; restores g_cnt_e/g_degx to zero
__global__ void k_prep(const int* __restrict__ batch, int n) {
    __shared__ int sh[256];
    __shared__ int base;
    int t = threadIdx.x;
    int i = blockIdx.x * 256 + t;
    int cnt = 0, cp = 0;
    if (i < n) {
        cnt = g_cnt_e[i];
        float deg = 1.0f + (float)cnt + g_degx[i];
        g_dinv[i] = rsqrtf(deg);
        atomicAdd(&g_cnt[batch[i]], 1);
        cp = (cnt + 3) & ~3;
        g_cnt_e[i] = 0;                 // restore invariant for next call
        g_degx[i] = 0.0f;
    }
    sh[t] = cp; __syncthreads();
    for (int d = 1; d < 256; d <<= 1) {
        int a = (t >= d) ? sh[t - d] : 0;
        __syncthreads();
        sh[t] += a;
        __syncthreads();
    }
    if (t == 255) base = atomicAdd(&g_total, sh[255]);
    __syncthreads();
    if (i < n) {
        int off = base + sh[t] - cp;
        g_offcnt[i] = make_int2(off, cnt);
        for (int z = cnt; z < cp; z++) g_srt[off + z] = 0u;
    }
}

// 4-edge-batched scatter at g_off[col] + rank (no atomics)
__global__ void k_scatter(const int* __restrict__ row, const int* __restrict__ col,
                          const float* __restrict__ ew, int e) {
    int t = blockIdx.x * blockDim.x + threadIdx.x;
    int base = t * 4;
    if ((e & 3) == 0) {
        if (base >= e) return;
        int4    r4 = __ldg(reinterpret_cast<const int4*>(row) + t);
        int4    c4 = __ldg(reinterpret_cast<const int4*>(col) + t);
        float4  w4 = __ldg(reinterpret_cast<const float4*>(ew) + t);
        ushort4 rk = reinterpret_cast<const ushort4*>(g_rank)[t];
        // 4 off-gathers in flight
        int o0 = __ldg(&g_offcnt[c4.x].x);
        int o1 = __ldg(&g_offcnt[c4.y].x);
        int o2 = __ldg(&g_offcnt[c4.z].x);
        int o3 = __ldg(&g_offcnt[c4.w].x);
        // 4 dinv gathers in flight
        float d0 = __ldg(&g_dinv[r4.x]);
        float d1 = __ldg(&g_dinv[r4.y]);
        float d2 = __ldg(&g_dinv[r4.z]);
        float d3 = __ldg(&g_dinv[r4.w]);
        unsigned int u0 = ((unsigned int)(__half_as_ushort(__float2half(d0 * w4.x)) & 0x7FFF) << 17) | (unsigned int)r4.x;
        unsigned int u1 = ((unsigned int)(__half_as_ushort(__float2half(d1 * w4.y)) & 0x7FFF) << 17) | (unsigned int)r4.y;
        unsigned int u2 = ((unsigned int)(__half_as_ushort(__float2half(d2 * w4.z)) & 0x7FFF) << 17) | (unsigned int)r4.z;
        unsigned int u3 = ((unsigned int)(__half_as_ushort(__float2half(d3 * w4.w)) & 0x7FFF) << 17) | (unsigned int)r4.w;
        g_srt[o0 + rk.x] = u0;
        g_srt[o1 + rk.y] = u1;
        g_srt[o2 + rk.z] = u2;
        g_srt[o3 + rk.w] = u3;
    } else {
        for (int m = 0; m < 4; m++) {
            int ei_ = base + m;
            if (ei_ < e) {
                int r = row[ei_], c = col[ei_];
                float w = __ldg(&g_dinv[r]) * ew[ei_];
                unsigned short hb = (unsigned short)(__half_as_ushort(__float2half(w)) & 0x7FFF);
                g_srt[__ldg(&g_offcnt[c].x) + (int)g_rank[ei_]] = ((unsigned int)hb << 17) | (unsigned int)r;
            }
        }
    }
}

// gather hop (unchanged from R8): fp8 storage, HFMA2, record-quad double buffered
template<bool POOL>
__global__ __launch_bounds__(256)
void k_hop(const unsigned char* __restrict__ hin, unsigned char* __restrict__ hout,
           const int* __restrict__ batch, int n) {
    int t = blockIdx.x * blockDim.x + threadIdx.x;
    int i = t >> 2, q = t & 3;
    if (i >= n) return;
    const uint4* hin4 = reinterpret_cast<const uint4*>(hin);

    __half2 selfh[8];
    fp8x16_to_h2(__ldg(hin4 + i * 4 + q), selfh);

    __half2 acc[8];
#pragma unroll
    for (int k = 0; k < 8; k++) acc[k] = __float2half2_rn(0.0f);

    int2 oc = __ldg(&g_offcnt[i]);
    int beg4 = oc.x >> 2;
    int nq   = (oc.y + 3) >> 2;
    const uint4* srt4 = reinterpret_cast<const uint4*>(g_srt);

    if (nq > 0) {
        uint4 e4 = __ldg(srt4 + beg4);
        for (int j = 0; j < nq; j++) {
            unsigned int es[4] = { e4.x, e4.y, e4.z, e4.w };
            if (j + 1 < nq) e4 = __ldg(srt4 + beg4 + j + 1);
#pragma unroll
            for (int m = 0; m < 4; m++) {
                unsigned int u = es[m];
                int r = (int)(u & 0x1FFFF);
                __half2 w2 = __half2half2(__ushort_as_half((unsigned short)(u >> 17)));
                uint4 hv = __ldg(hin4 + r * 4 + q);
                const __nv_fp8x2_storage_t* p = reinterpret_cast<const __nv_fp8x2_storage_t*>(&hv);
#pragma unroll
                for (int k = 0; k < 8; k++) {
                    __half2_raw hr = __nv_cvt_fp8x2_to_halfraw2(p[k], __NV_E4M3);
                    acc[k] = __hfma2(w2, *reinterpret_cast<__half2*>(&hr), acc[k]);
                }
            }
        }
    }

    float s = g_dinv[i];
    float s2 = s * s;
    float o[16];
#pragma unroll
    for (int k = 0; k < 8; k++) {
        float2 sf = __half22float2(selfh[k]);
        float2 af = __half22float2(acc[k]);
        o[2*k]   = sf.x * s2 + s * af.x;
        o[2*k+1] = sf.y * s2 + s * af.y;
    }

    if (POOL) {
        int b = batch[i];
        float* base = g_pool + b * FF + q * 16;
#pragma unroll
        for (int k = 0; k < 4; k++)
            red_add_v4(base + 4*k, make_float4(o[4*k], o[4*k+1], o[4*k+2], o[4*k+3]));
    } else {
        reinterpret_cast<uint4*>(hout)[i * 4 + q] = f16_to_fp8x16(o);
    }
}

// head; also restores g_pool/g_cnt/g_total invariants
__global__ void k_head(const float* __restrict__ conv_w, const float* __restrict__ conv_b,
                       const float* __restrict__ lin1_w, const float* __restrict__ lin1_b,
                       const float* __restrict__ lin2_w, const float* __restrict__ lin2_b,
                       float* __restrict__ out) {
    int g = blockIdx.x;
    int f = threadIdx.x;
    __shared__ float sh_t[FF];
    __shared__ float sh_h1[FF];
    __shared__ float sh_h2[FF];
    __shared__ float sh_z[CC];

    float invc = 1.0f / (SCALE * fmaxf((float)g_cnt[g], 1.0f));
    sh_t[f] = g_pool[g * FF + f] * invc;
    __syncthreads();
    // restore invariants (all reads of pool/cnt are done)
    g_pool[g * FF + f] = 0.0f;
    if (f == 0) g_cnt[g] = 0;
    if (g == 0 && f == 0) g_total = 0;

    float a = conv_b[f];
#pragma unroll
    for (int k = 0; k < FF; k++) a += sh_t[k] * conv_w[k * FF + f];
    sh_h1[f] = a;
    __syncthreads();

    float b = lin1_b[f];
#pragma unroll
    for (int k = 0; k < FF; k++) b += sh_h1[k] * lin1_w[k * FF + f];
    sh_h2[f] = fmaxf(b, 0.0f);
    __syncthreads();

    if (f < CC) {
        float c = lin2_b[f];
#pragma unroll
        for (int k = 0; k < FF; k++) c += sh_h2[k] * lin2_w[k * CC + f];
        sh_z[f] = c;
    }
    __syncthreads();

    if (f < CC) {
        float m = -INFINITY;
#pragma unroll
        for (int j = 0; j < CC; j++) m = fmaxf(m, sh_z[j]);
        float s = 0.0f;
#pragma unroll
        for (int j = 0; j < CC; j++) s += expf(sh_z[j] - m);
        out[g * CC + f] = sh_z[f] - m - logf(s);
    }
}

// ---------------- launch ----------------
extern "C" void kernel_launch(void* const* d_in, const int* in_sizes, int n_in,
                              void* d_out, int out_size) {
    const float* x      = (const float*)d_in[0];
    const int*   ei     = (const int*)d_in[1];
    const float* ew     = (const float*)d_in[2];
    const int*   batch  = (const int*)d_in[3];
    const float* conv_w = (const float*)d_in[4];
    const float* conv_b = (const float*)d_in[5];
    const float* lin1_w = (const float*)d_in[6];
    const float* lin1_b = (const float*)d_in[7];
    const float* lin2_w = (const float*)d_in[8];
    const float* lin2_b = (const float*)d_in[9];
    float* out = (float*)d_out;

    int n = in_sizes[3];
    int e = in_sizes[2];
    const int* row = ei;
    const int* col = ei + e;

    unsigned char *x8, *ha, *hb;
    cudaGetSymbolAddress((void**)&x8, g_x8);
    cudaGetSymbolAddress((void**)&ha, g_ha);
    cudaGetSymbolAddress((void**)&hb, g_hb);

    const int TB = 256;
    int grid_n  = (n + TB - 1) / TB;
    int e4      = (e + 3) / 4;
    int cd_thr  = (n * 4 > e4) ? n * 4 : e4;
    int grid_cd = (cd_thr + TB - 1) / TB;
    int grid_s  = (e4 + TB - 1) / TB;
    int grid_n4 = (n * 4 + TB - 1) / TB;

    k_cvt_deg<<<grid_cd, TB>>>(x, col, ew, n, e);
    k_prep<<<grid_n, TB>>>(batch, n);
    k_scatter<<<grid_s, TB>>>(row, col, ew, e);

    k_hop<false><<<grid_n4, TB>>>(x8, ha, batch, n);
    k_hop<false><<<grid_n4, TB>>>(ha, hb, batch, n);
    k_hop<true ><<<grid_n4, TB>>>(hb, (unsigned char*)nullptr, batch, n);

    k_head<<<GG, FF>>>(conv_w, conv_b, lin1_w, lin1_b, lin2_w, lin2_b, out);
}

// round 11
// speedup vs baseline: 1.1250x; 1.0506x over previous
#include <cuda_runtime.h>
#include <cuda_fp16.h>
#include <cuda_fp8.h>
#include <math.h>

#define NN 100000
#define EE 1600000
#define EPAD 1750016          // >= EE + NN, even
#define FF 64
#define GG 512
#define CC 10
#define SCALE 16.0f

// ---------------- device scratch (zero-init at load; consumers restore) ----------------
__device__ __align__(128) unsigned char g_x8[NN * FF];
__device__ __align__(128) unsigned char g_ha[NN * FF];
__device__ __align__(128) unsigned char g_hb[NN * FF];
__device__ float g_dinv[NN];
__device__ float g_degx[NN];            // zeroed by k_prep after read
__device__ int   g_cnt_e[NN];           // zeroed by k_prep after read
__device__ __align__(8) int2 g_offcnt[NN];
__device__ __align__(8) unsigned short g_rank[EE];
__device__ __align__(16) uint2 g_srt[EPAD];   // (w packed half2, row*4)
__device__ int   g_total;               // zeroed by k_head
__device__ int   g_wflag;               // set by k_deg if any ew!=1; zeroed by k_head
__device__ __align__(16) float g_pool[GG * FF];   // zeroed by k_head after read
__device__ int   g_cnt[GG];             // zeroed by k_head after read

__device__ __forceinline__ void red_add_v4(float* addr, float4 v) {
    asm volatile("red.global.add.v4.f32 [%0], {%1, %2, %3, %4};"
                 :: "l"(addr), "f"(v.x), "f"(v.y), "f"(v.z), "f"(v.w)
                 : "memory");
}

__device__ __forceinline__ void fp8x16_to_h2(uint4 u, __half2* h) {
    const __nv_fp8x2_storage_t* p = reinterpret_cast<const __nv_fp8x2_storage_t*>(&u);
#pragma unroll
    for (int k = 0; k < 8; k++) {
        __half2_raw hr = __nv_cvt_fp8x2_to_halfraw2(p[k], __NV_E4M3);
        h[k] = *reinterpret_cast<__half2*>(&hr);
    }
}
__device__ __forceinline__ uint4 f16_to_fp8x16(const float* f) {
    uint4 u;
    __nv_fp8x2_storage_t* p = reinterpret_cast<__nv_fp8x2_storage_t*>(&u);
#pragma unroll
    for (int k = 0; k < 8; k++)
        p[k] = __nv_cvt_float2_to_fp8x2(make_float2(f[2*k], f[2*k+1]), __NV_SATFINITE, __NV_E4M3);
    return u;
}

__device__ __forceinline__ unsigned int pack_w(float w) {
    unsigned short h = __half_as_ushort(__float2half(w));
    return (unsigned int)h | ((unsigned int)h << 16);
}

// ---------------- kernels ----------------

// 4-edge-batched degree/rank (+ wflag)
__global__ void k_deg(const int* __restrict__ col, const float* __restrict__ ew, int e) {
    int t = blockIdx.x * blockDim.x + threadIdx.x;
    int base = t * 4;
    if ((e & 3) == 0) {
        if (base >= e) return;
        int4   c4 = __ldg(reinterpret_cast<const int4*>(col) + t);
        float4 w4 = __ldg(reinterpret_cast<const float4*>(ew) + t);
        ushort4 rk;
        rk.x = (unsigned short)atomicAdd(&g_cnt_e[c4.x], 1);
        rk.y = (unsigned short)atomicAdd(&g_cnt_e[c4.y], 1);
        rk.z = (unsigned short)atomicAdd(&g_cnt_e[c4.z], 1);
        rk.w = (unsigned short)atomicAdd(&g_cnt_e[c4.w], 1);
        if (w4.x != 1.0f) { atomicAdd(&g_degx[c4.x], w4.x - 1.0f); g_wflag = 1; }
        if (w4.y != 1.0f) { atomicAdd(&g_degx[c4.y], w4.y - 1.0f); g_wflag = 1; }
        if (w4.z != 1.0f) { atomicAdd(&g_degx[c4.z], w4.z - 1.0f); g_wflag = 1; }
        if (w4.w != 1.0f) { atomicAdd(&g_degx[c4.w], w4.w - 1.0f); g_wflag = 1; }
        reinterpret_cast<ushort4*>(g_rank)[t] = rk;
    } else {
        for (int m = 0; m < 4; m++) {
            int ei_ = base + m;
            if (ei_ < e) {
                int c = col[ei_];
                g_rank[ei_] = (unsigned short)atomicAdd(&g_cnt_e[c], 1);
                float w = ew[ei_];
                if (w != 1.0f) { atomicAdd(&g_degx[c], w - 1.0f); g_wflag = 1; }
            }
        }
    }
}

// dinv + batch counts + even-padded exclusive scan; restores g_cnt_e/g_degx
__global__ void k_prep(const int* __restrict__ batch, int n) {
    __shared__ int sh[256];
    __shared__ int base;
    int t = threadIdx.x;
    int i = blockIdx.x * 256 + t;
    int cnt = 0, cp = 0;
    if (i < n) {
        cnt = g_cnt_e[i];
        float deg = 1.0f + (float)cnt + g_degx[i];
        g_dinv[i] = rsqrtf(deg);
        atomicAdd(&g_cnt[batch[i]], 1);
        cp = (cnt + 1) & ~1;            // pad bucket to even (2 records per uint4)
        g_cnt_e[i] = 0;
        g_degx[i] = 0.0f;
    }
    sh[t] = cp; __syncthreads();
    for (int d = 1; d < 256; d <<= 1) {
        int a = (t >= d) ? sh[t - d] : 0;
        __syncthreads();
        sh[t] += a;
        __syncthreads();
    }
    if (t == 255) base = atomicAdd(&g_total, sh[255]);
    __syncthreads();
    if (i < n) {
        int off = base + sh[t] - cp;
        g_offcnt[i] = make_int2(off, cnt);
        for (int z = cnt; z < cp; z++) g_srt[off + z] = make_uint2(0u, 0u); // w=0, row=0
    }
}

// fused: x -> fp8(dinv*x*SCALE) + 4-edge-batched scatter of (w_half2, row*4) records
__global__ void k_cvt_scatter(const float* __restrict__ x,
                              const int* __restrict__ row, const int* __restrict__ col,
                              const float* __restrict__ ew, int n, int e) {
    int t = blockIdx.x * blockDim.x + threadIdx.x;
    if (t < n * 4) {
        int i = t >> 2;
        float di = __ldg(&g_dinv[i]) * SCALE;
        const float4* xp = reinterpret_cast<const float4*>(x) + t * 4;
        float f[16];
#pragma unroll
        for (int k = 0; k < 4; k++) {
            float4 v = __ldg(xp + k);
            f[4*k+0] = v.x * di; f[4*k+1] = v.y * di;
            f[4*k+2] = v.z * di; f[4*k+3] = v.w * di;
        }
        reinterpret_cast<uint4*>(g_x8)[t] = f16_to_fp8x16(f);
    }
    int base = t * 4;
    int wf = g_wflag;
    if ((e & 3) == 0) {
        if (base < e) {
            int4    r4 = __ldg(reinterpret_cast<const int4*>(row) + t);
            int4    c4 = __ldg(reinterpret_cast<const int4*>(col) + t);
            ushort4 rk = reinterpret_cast<const ushort4*>(g_rank)[t];
            int o0 = __ldg(&g_offcnt[c4.x].x);
            int o1 = __ldg(&g_offcnt[c4.y].x);
            int o2 = __ldg(&g_offcnt[c4.z].x);
            int o3 = __ldg(&g_offcnt[c4.w].x);
            unsigned int w0, w1, w2, w3;
            if (wf) {
                float4 w4 = __ldg(reinterpret_cast<const float4*>(ew) + t);
                w0 = pack_w(w4.x); w1 = pack_w(w4.y); w2 = pack_w(w4.z); w3 = pack_w(w4.w);
            } else {
                w0 = w1 = w2 = w3 = 0x3C003C00u;   // half2(1.0, 1.0)
            }
            g_srt[o0 + rk.x] = make_uint2(w0, (unsigned int)(r4.x * 4));
            g_srt[o1 + rk.y] = make_uint2(w1, (unsigned int)(r4.y * 4));
            g_srt[o2 + rk.z] = make_uint2(w2, (unsigned int)(r4.z * 4));
            g_srt[o3 + rk.w] = make_uint2(w3, (unsigned int)(r4.w * 4));
        }
    } else {
        for (int m = 0; m < 4; m++) {
            int ei_ = base + m;
            if (ei_ < e) {
                int r = row[ei_], c = col[ei_];
                unsigned int wp = wf ? pack_w(ew[ei_]) : 0x3C003C00u;
                g_srt[__ldg(&g_offcnt[c].x) + (int)g_rank[ei_]] = make_uint2(wp, (unsigned int)(r * 4));
            }
        }
    }
}

// gather hop (g-form): out = dinv^p * (self + sum w*g[row]); p=2 normal, p=1 pool hop
template<bool POOL>
__global__ __launch_bounds__(256, 5)
void k_hop(const unsigned char* __restrict__ hin, unsigned char* __restrict__ hout,
           const int* __restrict__ batch, int n) {
    int t = blockIdx.x * blockDim.x + threadIdx.x;
    int i = t >> 2, q = t & 3;
    if (i >= n) return;
    const uint4* hin4 = reinterpret_cast<const uint4*>(hin);

    __half2 acc[8];
    fp8x16_to_h2(__ldg(hin4 + i * 4 + q), acc);   // acc = self term (weight 1)

    int2 oc = __ldg(&g_offcnt[i]);
    int begq = oc.x >> 1;                          // uint4 index (2 records each)
    int nq   = (oc.y + 1) >> 1;
    const uint4* srt4 = reinterpret_cast<const uint4*>(g_srt);

    if (nq > 0) {
        uint4 e4 = __ldg(srt4 + begq);
        for (int j = 0; j < nq; j++) {
            uint4 cur = e4;
            if (j + 1 < nq) e4 = __ldg(srt4 + begq + j + 1);
            __half2 w20 = *reinterpret_cast<__half2*>(&cur.x);
            __half2 w21 = *reinterpret_cast<__half2*>(&cur.z);
            uint4 hv0 = __ldg(hin4 + (int)cur.y + q);
            uint4 hv1 = __ldg(hin4 + (int)cur.w + q);
            const __nv_fp8x2_storage_t* p0 = reinterpret_cast<const __nv_fp8x2_storage_t*>(&hv0);
            const __nv_fp8x2_storage_t* p1 = reinterpret_cast<const __nv_fp8x2_storage_t*>(&hv1);
#pragma unroll
            for (int k = 0; k < 8; k++) {
                __half2_raw hr0 = __nv_cvt_fp8x2_to_halfraw2(p0[k], __NV_E4M3);
                acc[k] = __hfma2(w20, *reinterpret_cast<__half2*>(&hr0), acc[k]);
            }
#pragma unroll
            for (int k = 0; k < 8; k++) {
                __half2_raw hr1 = __nv_cvt_fp8x2_to_halfraw2(p1[k], __NV_E4M3);
                acc[k] = __hfma2(w21, *reinterpret_cast<__half2*>(&hr1), acc[k]);
            }
        }
    }

    float s = g_dinv[i];
    float sp = POOL ? s : s * s;
    float o[16];
#pragma unroll
    for (int k = 0; k < 8; k++) {
        float2 af = __half22float2(acc[k]);
        o[2*k]   = af.x * sp;
        o[2*k+1] = af.y * sp;
    }

    if (POOL) {
        int b = batch[i];
        float* base = g_pool + b * FF + q * 16;
#pragma unroll
        for (int k = 0; k < 4; k++)
            red_add_v4(base + 4*k, make_float4(o[4*k], o[4*k+1], o[4*k+2], o[4*k+3]));
    } else {
        reinterpret_cast<uint4*>(hout)[i * 4 + q] = f16_to_fp8x16(o);
    }
}

// head; restores g_pool/g_cnt/g_total/g_wflag invariants
__global__ void k_head(const float* __restrict__ conv_w, const float* __restrict__ conv_b,
                       const float* __restrict__ lin1_w, const float* __restrict__ lin1_b,
                       const float* __restrict__ lin2_w, const float* __restrict__ lin2_b,
                       float* __restrict__ out) {
    int g = blockIdx.x;
    int f = threadIdx.x;
    __shared__ float sh_t[FF];
    __shared__ float sh_h1[FF];
    __shared__ float sh_h2[FF];
    __shared__ float sh_z[CC];

    float invc = 1.0f / (SCALE * fmaxf((float)g_cnt[g], 1.0f));
    sh_t[f] = g_pool[g * FF + f] * invc;
    __syncthreads();
    g_pool[g * FF + f] = 0.0f;
    if (f == 0) g_cnt[g] = 0;
    if (g == 0 && f == 0) { g_total = 0; g_wflag = 0; }

    float a = conv_b[f];
#pragma unroll
    for (int k = 0; k < FF; k++) a += sh_t[k] * conv_w[k * FF + f];
    sh_h1[f] = a;
    __syncthreads();

    float b = lin1_b[f];
#pragma unroll
    for (int k = 0; k < FF; k++) b += sh_h1[k] * lin1_w[k * FF + f];
    sh_h2[f] = fmaxf(b, 0.0f);
    __syncthreads();

    if (f < CC) {
        float c = lin2_b[f];
#pragma unroll
        for (int k = 0; k < FF; k++) c += sh_h2[k] * lin2_w[k * CC + f];
        sh_z[f] = c;
    }
    __syncthreads();

    if (f < CC) {
        float m = -INFINITY;
#pragma unroll
        for (int j = 0; j < CC; j++) m = fmaxf(m, sh_z[j]);
        float s = 0.0f;
#pragma unroll
        for (int j = 0; j < CC; j++) s += expf(sh_z[j] - m);
        out[g * CC + f] = sh_z[f] - m - logf(s);
    }
}

// ---------------- launch ----------------
extern "C" void kernel_launch(void* const* d_in, const int* in_sizes, int n_in,
                              void* d_out, int out_size) {
    const float* x      = (const float*)d_in[0];
    const int*   ei     = (const int*)d_in[1];
    const float* ew     = (const float*)d_in[2];
    const int*   batch  = (const int*)d_in[3];
    const float* conv_w = (const float*)d_in[4];
    const float* conv_b = (const float*)d_in[5];
    const float* lin1_w = (const float*)d_in[6];
    const float* lin1_b = (const float*)d_in[7];
    const float* lin2_w = (const float*)d_in[8];
    const float* lin2_b = (const float*)d_in[9];
    float* out = (float*)d_out;

    int n = in_sizes[3];
    int e = in_sizes[2];
    const int* row = ei;
    const int* col = ei + e;

    unsigned char *x8, *ha, *hb;
    cudaGetSymbolAddress((void**)&x8, g_x8);
    cudaGetSymbolAddress((void**)&ha, g_ha);
    cudaGetSymbolAddress((void**)&hb, g_hb);

    const int TB = 256;
    int grid_n  = (n + TB - 1) / TB;
    int e4      = (e + 3) / 4;
    int grid_d  = (e4 + TB - 1) / TB;
    int cs_thr  = (n * 4 > e4) ? n * 4 : e4;
    int grid_cs = (cs_thr + TB - 1) / TB;
    int grid_n4 = (n * 4 + TB - 1) / TB;

    k_deg<<<grid_d, TB>>>(col, ew, e);
    k_prep<<<grid_n, TB>>>(batch, n);
    k_cvt_scatter<<<grid_cs, TB>>>(x, row, col, ew, n, e);

    k_hop<false><<<grid_n4, TB>>>(x8, ha, batch, n);
    k_hop<false><<<grid_n4, TB>>>(ha, hb, batch, n);
    k_hop<true ><<<grid_n4, TB>>>(hb, (unsigned char*)nullptr, batch, n);

    k_head<<<GG, FF>>>(conv_w, conv_b, lin1_w, lin1_b, lin2_w, lin2_b, out);
}

// round 12
// speedup vs baseline: 1.1685x; 1.0386x over previous
#include <cuda_runtime.h>
#include <cuda_fp16.h>
#include <cuda_fp8.h>
#include <math.h>

#define NN 100000
#define EE 1600000
#define EPAD 1750016          // >= EE + NN, even
#define FF 64
#define GG 512
#define CC 10
#define NB 1024               // degree buckets
#define SCALE 16.0f

// ---------------- device scratch (zero-init at load; consumers restore) ----------------
__device__ __align__(128) unsigned char g_x8[NN * FF];
__device__ __align__(128) unsigned char g_ha[NN * FF];
__device__ __align__(128) unsigned char g_hb[NN * FF];
__device__ float g_dinv[NN];
__device__ float g_degx[NN];            // zeroed by k_prep after read
__device__ int   g_cnt_e[NN];           // zeroed by k_prep after read
__device__ __align__(8) int2 g_offcnt[NN];
__device__ __align__(8) unsigned short g_rank[EE];
__device__ __align__(16) uint2 g_srt[EPAD];   // (w packed half2, row*4)
__device__ int   g_total;               // zeroed by k_head
__device__ int   g_wflag;               // zeroed by k_head
__device__ int   g_dhist[NB];           // zeroed by k_scan after read
__device__ int   g_dboff[NB];
__device__ int   g_drank[NN];
__device__ int   g_perm[NN];
__device__ __align__(16) float g_pool[GG * FF];   // zeroed by k_head after read
__device__ int   g_cnt[GG];             // zeroed by k_head after read

__device__ __forceinline__ void red_add_v4(float* addr, float4 v) {
    asm volatile("red.global.add.v4.f32 [%0], {%1, %2, %3, %4};"
                 :: "l"(addr), "f"(v.x), "f"(v.y), "f"(v.z), "f"(v.w)
                 : "memory");
}

__device__ __forceinline__ void fp8x16_to_h2(uint4 u, __half2* h) {
    const __nv_fp8x2_storage_t* p = reinterpret_cast<const __nv_fp8x2_storage_t*>(&u);
#pragma unroll
    for (int k = 0; k < 8; k++) {
        __half2_raw hr = __nv_cvt_fp8x2_to_halfraw2(p[k], __NV_E4M3);
        h[k] = *reinterpret_cast<__half2*>(&hr);
    }
}
__device__ __forceinline__ uint4 f16_to_fp8x16(const float* f) {
    uint4 u;
    __nv_fp8x2_storage_t* p = reinterpret_cast<__nv_fp8x2_storage_t*>(&u);
#pragma unroll
    for (int k = 0; k < 8; k++)
        p[k] = __nv_cvt_float2_to_fp8x2(make_float2(f[2*k], f[2*k+1]), __NV_SATFINITE, __NV_E4M3);
    return u;
}

__device__ __forceinline__ unsigned int pack_w(float w) {
    unsigned short h = __half_as_ushort(__float2half(w));
    return (unsigned int)h | ((unsigned int)h << 16);
}

// ---------------- kernels ----------------

// 4-edge-batched degree/rank (+ wflag)
__global__ void k_deg(const int* __restrict__ col, const float* __restrict__ ew, int e) {
    int t = blockIdx.x * blockDim.x + threadIdx.x;
    int base = t * 4;
    if ((e & 3) == 0) {
        if (base >= e) return;
        int4   c4 = __ldg(reinterpret_cast<const int4*>(col) + t);
        float4 w4 = __ldg(reinterpret_cast<const float4*>(ew) + t);
        ushort4 rk;
        rk.x = (unsigned short)atomicAdd(&g_cnt_e[c4.x], 1);
        rk.y = (unsigned short)atomicAdd(&g_cnt_e[c4.y], 1);
        rk.z = (unsigned short)atomicAdd(&g_cnt_e[c4.z], 1);
        rk.w = (unsigned short)atomicAdd(&g_cnt_e[c4.w], 1);
        if (w4.x != 1.0f) { atomicAdd(&g_degx[c4.x], w4.x - 1.0f); g_wflag = 1; }
        if (w4.y != 1.0f) { atomicAdd(&g_degx[c4.y], w4.y - 1.0f); g_wflag = 1; }
        if (w4.z != 1.0f) { atomicAdd(&g_degx[c4.z], w4.z - 1.0f); g_wflag = 1; }
        if (w4.w != 1.0f) { atomicAdd(&g_degx[c4.w], w4.w - 1.0f); g_wflag = 1; }
        reinterpret_cast<ushort4*>(g_rank)[t] = rk;
    } else {
        for (int m = 0; m < 4; m++) {
            int ei_ = base + m;
            if (ei_ < e) {
                int c = col[ei_];
                g_rank[ei_] = (unsigned short)atomicAdd(&g_cnt_e[c], 1);
                float w = ew[ei_];
                if (w != 1.0f) { atomicAdd(&g_degx[c], w - 1.0f); g_wflag = 1; }
            }
        }
    }
}

// dinv + batch counts + padded offset scan + degree-bucket histogram/rank
__global__ void k_prep(const int* __restrict__ batch, int n) {
    __shared__ int sh[256];
    __shared__ int base;
    __shared__ int lh[NB];     // block-local bucket histogram
    __shared__ int lb[NB];     // block's base in each global bucket
    int t = threadIdx.x;
    int i = blockIdx.x * 256 + t;
#pragma unroll
    for (int k = 0; k < NB / 256; k++) lh[t + k * 256] = 0;
    __syncthreads();

    int cnt = 0, cp = 0, db = 0, lrank = 0;
    if (i < n) {
        cnt = g_cnt_e[i];
        float deg = 1.0f + (float)cnt + g_degx[i];
        g_dinv[i] = rsqrtf(deg);
        atomicAdd(&g_cnt[batch[i]], 1);
        cp = (cnt + 1) & ~1;
        g_cnt_e[i] = 0;
        g_degx[i] = 0.0f;
        int nq = cp >> 1;                       // exact hop iteration count
        db = (nq < NB) ? nq : (NB - 1);
        lrank = atomicAdd(&lh[db], 1);
    }
    __syncthreads();
#pragma unroll
    for (int k = 0; k < NB / 256; k++) {
        int b = t + k * 256;
        if (lh[b] > 0) lb[b] = atomicAdd(&g_dhist[b], lh[b]);
    }
    // offset scan
    sh[t] = cp; __syncthreads();
    for (int d = 1; d < 256; d <<= 1) {
        int a = (t >= d) ? sh[t - d] : 0;
        __syncthreads();
        sh[t] += a;
        __syncthreads();
    }
    if (t == 255) base = atomicAdd(&g_total, sh[255]);
    __syncthreads();
    if (i < n) {
        int off = base + sh[t] - cp;
        g_offcnt[i] = make_int2(off, cnt);
        for (int z = cnt; z < cp; z++) g_srt[off + z] = make_uint2(0u, 0u);
        g_drank[i] = lb[db] + lrank;
    }
}

// single-block exclusive scan of bucket histogram; restores g_dhist to zero
__global__ void k_scan(void) {
    __shared__ int sh[NB];
    int t = threadIdx.x;
    int v = g_dhist[t];
    g_dhist[t] = 0;                    // restore invariant
    sh[t] = v; __syncthreads();
    for (int d = 1; d < NB; d <<= 1) {
        int a = (t >= d) ? sh[t - d] : 0;
        __syncthreads();
        sh[t] += a;
        __syncthreads();
    }
    g_dboff[t] = sh[t] - v;
}

// fused: x -> fp8(dinv*x*SCALE) + perm scatter + 4-edge-batched edge-record scatter
__global__ void k_cvt_scatter(const float* __restrict__ x,
                              const int* __restrict__ row, const int* __restrict__ col,
                              const float* __restrict__ ew, int n, int e) {
    int t = blockIdx.x * blockDim.x + threadIdx.x;
    if (t < n * 4) {
        int i = t >> 2;
        float di = __ldg(&g_dinv[i]) * SCALE;
        const float4* xp = reinterpret_cast<const float4*>(x) + t * 4;
        float f[16];
#pragma unroll
        for (int k = 0; k < 4; k++) {
            float4 v = __ldg(xp + k);
            f[4*k+0] = v.x * di; f[4*k+1] = v.y * di;
            f[4*k+2] = v.z * di; f[4*k+3] = v.w * di;
        }
        reinterpret_cast<uint4*>(g_x8)[t] = f16_to_fp8x16(f);
    }
    if (t < n) {                                   // degree-sorted permutation
        int cnt = g_offcnt[t].y;
        int nq = (cnt + 1) >> 1;
        int db = (nq < NB) ? nq : (NB - 1);
        g_perm[__ldg(&g_dboff[db]) + g_drank[t]] = t;
    }
    int base = t * 4;
    int wf = g_wflag;
    if ((e & 3) == 0) {
        if (base < e) {
            int4    r4 = __ldg(reinterpret_cast<const int4*>(row) + t);
            int4    c4 = __ldg(reinterpret_cast<const int4*>(col) + t);
            ushort4 rk = reinterpret_cast<const ushort4*>(g_rank)[t];
            int o0 = __ldg(&g_offcnt[c4.x].x);
            int o1 = __ldg(&g_offcnt[c4.y].x);
            int o2 = __ldg(&g_offcnt[c4.z].x);
            int o3 = __ldg(&g_offcnt[c4.w].x);
            unsigned int w0, w1, w2, w3;
            if (wf) {
                float4 w4 = __ldg(reinterpret_cast<const float4*>(ew) + t);
                w0 = pack_w(w4.x); w1 = pack_w(w4.y); w2 = pack_w(w4.z); w3 = pack_w(w4.w);
            } else {
                w0 = w1 = w2 = w3 = 0x3C003C00u;
            }
            g_srt[o0 + rk.x] = make_uint2(w0, (unsigned int)(r4.x * 4));
            g_srt[o1 + rk.y] = make_uint2(w1, (unsigned int)(r4.y * 4));
            g_srt[o2 + rk.z] = make_uint2(w2, (unsigned int)(r4.z * 4));
            g_srt[o3 + rk.w] = make_uint2(w3, (unsigned int)(r4.w * 4));
        }
    } else {
        for (int m = 0; m < 4; m++) {
            int ei_ = base + m;
            if (ei_ < e) {
                int r = row[ei_], c = col[ei_];
                unsigned int wp = wf ? pack_w(ew[ei_]) : 0x3C003C00u;
                g_srt[__ldg(&g_offcnt[c].x) + (int)g_rank[ei_]] = make_uint2(wp, (unsigned int)(r * 4));
            }
        }
    }
}

// gather hop over degree-sorted nodes: out = dinv^p * (self + sum w*g[row])
template<bool POOL>
__global__ __launch_bounds__(256, 5)
void k_hop(const unsigned char* __restrict__ hin, unsigned char* __restrict__ hout,
           const int* __restrict__ batch, int n) {
    int t = blockIdx.x * blockDim.x + threadIdx.x;
    int ii = t >> 2, q = t & 3;
    if (ii >= n) return;
    int i = __ldg(&g_perm[ii]);
    const uint4* hin4 = reinterpret_cast<const uint4*>(hin);

    __half2 acc[8];
    fp8x16_to_h2(__ldg(hin4 + i * 4 + q), acc);   // self term (weight 1)

    int2 oc = __ldg(&g_offcnt[i]);
    int begq = oc.x >> 1;
    int nq   = (oc.y + 1) >> 1;
    const uint4* srt4 = reinterpret_cast<const uint4*>(g_srt);

    if (nq > 0) {
        uint4 e4 = __ldg(srt4 + begq);
        for (int j = 0; j < nq; j++) {
            uint4 cur = e4;
            if (j + 1 < nq) e4 = __ldg(srt4 + begq + j + 1);
            __half2 w20 = *reinterpret_cast<__half2*>(&cur.x);
            __half2 w21 = *reinterpret_cast<__half2*>(&cur.z);
            uint4 hv0 = __ldg(hin4 + (int)cur.y + q);
            uint4 hv1 = __ldg(hin4 + (int)cur.w + q);
            const __nv_fp8x2_storage_t* p0 = reinterpret_cast<const __nv_fp8x2_storage_t*>(&hv0);
            const __nv_fp8x2_storage_t* p1 = reinterpret_cast<const __nv_fp8x2_storage_t*>(&hv1);
#pragma unroll
            for (int k = 0; k < 8; k++) {
                __half2_raw hr0 = __nv_cvt_fp8x2_to_halfraw2(p0[k], __NV_E4M3);
                acc[k] = __hfma2(w20, *reinterpret_cast<__half2*>(&hr0), acc[k]);
            }
#pragma unroll
            for (int k = 0; k < 8; k++) {
                __half2_raw hr1 = __nv_cvt_fp8x2_to_halfraw2(p1[k], __NV_E4M3);
                acc[k] = __hfma2(w21, *reinterpret_cast<__half2*>(&hr1), acc[k]);
            }
        }
    }

    float s = g_dinv[i];
    float sp = POOL ? s : s * s;
    float o[16];
#pragma unroll
    for (int k = 0; k < 8; k++) {
        float2 af = __half22float2(acc[k]);
        o[2*k]   = af.x * sp;
        o[2*k+1] = af.y * sp;
    }

    if (POOL) {
        int b = __ldg(&batch[i]);
        float* base = g_pool + b * FF + q * 16;
#pragma unroll
        for (int k = 0; k < 4; k++)
            red_add_v4(base + 4*k, make_float4(o[4*k], o[4*k+1], o[4*k+2], o[4*k+3]));
    } else {
        reinterpret_cast<uint4*>(hout)[i * 4 + q] = f16_to_fp8x16(o);
    }
}

// head; restores g_pool/g_cnt/g_total/g_wflag
__global__ void k_head(const float* __restrict__ conv_w, const float* __restrict__ conv_b,
                       const float* __restrict__ lin1_w, const float* __restrict__ lin1_b,
                       const float* __restrict__ lin2_w, const float* __restrict__ lin2_b,
                       float* __restrict__ out) {
    int g = blockIdx.x;
    int f = threadIdx.x;
    __shared__ float sh_t[FF];
    __shared__ float sh_h1[FF];
    __shared__ float sh_h2[FF];
    __shared__ float sh_z[CC];

    float invc = 1.0f / (SCALE * fmaxf((float)g_cnt[g], 1.0f));
    sh_t[f] = g_pool[g * FF + f] * invc;
    __syncthreads();
    g_pool[g * FF + f] = 0.0f;
    if (f == 0) g_cnt[g] = 0;
    if (g == 0 && f == 0) { g_total = 0; g_wflag = 0; }

    float a = conv_b[f];
#pragma unroll
    for (int k = 0; k < FF; k++) a += sh_t[k] * conv_w[k * FF + f];
    sh_h1[f] = a;
    __syncthreads();

    float b = lin1_b[f];
#pragma unroll
    for (int k = 0; k < FF; k++) b += sh_h1[k] * lin1_w[k * FF + f];
    sh_h2[f] = fmaxf(b, 0.0f);
    __syncthreads();

    if (f < CC) {
        float c = lin2_b[f];
#pragma unroll
        for (int k = 0; k < FF; k++) c += sh_h2[k] * lin2_w[k * CC + f];
        sh_z[f] = c;
    }
    __syncthreads();

    if (f < CC) {
        float m = -INFINITY;
#pragma unroll
        for (int j = 0; j < CC; j++) m = fmaxf(m, sh_z[j]);
        float s = 0.0f;
#pragma unroll
        for (int j = 0; j < CC; j++) s += expf(sh_z[j] - m);
        out[g * CC + f] = sh_z[f] - m - logf(s);
    }
}

// ---------------- launch ----------------
extern "C" void kernel_launch(void* const* d_in, const int* in_sizes, int n_in,
                              void* d_out, int out_size) {
    const float* x      = (const float*)d_in[0];
    const int*   ei     = (const int*)d_in[1];
    const float* ew     = (const float*)d_in[2];
    const int*   batch  = (const int*)d_in[3];
    const float* conv_w = (const float*)d_in[4];
    const float* conv_b = (const float*)d_in[5];
    const float* lin1_w = (const float*)d_in[6];
    const float* lin1_b = (const float*)d_in[7];
    const float* lin2_w = (const float*)d_in[8];
    const float* lin2_b = (const float*)d_in[9];
    float* out = (float*)d_out;

    int n = in_sizes[3];
    int e = in_sizes[2];
    const int* row = ei;
    const int* col = ei + e;

    unsigned char *x8, *ha, *hb;
    cudaGetSymbolAddress((void**)&x8, g_x8);
    cudaGetSymbolAddress((void**)&ha, g_ha);
    cudaGetSymbolAddress((void**)&hb, g_hb);

    const int TB = 256;
    int grid_n  = (n + TB - 1) / TB;
    int e4      = (e + 3) / 4;
    int grid_d  = (e4 + TB - 1) / TB;
    int cs_thr  = (n * 4 > e4) ? n * 4 : e4;
    int grid_cs = (cs_thr + TB - 1) / TB;
    int grid_n4 = (n * 4 + TB - 1) / TB;

    k_deg<<<grid_d, TB>>>(col, ew, e);
    k_prep<<<grid_n, TB>>>(batch, n);
    k_scan<<<1, NB>>>();
    k_cvt_scatter<<<grid_cs, TB>>>(x, row, col, ew, n, e);

    k_hop<false><<<grid_n4, TB>>>(x8, ha, batch, n);
    k_hop<false><<<grid_n4, TB>>>(ha, hb, batch, n);
    k_hop<true ><<<grid_n4, TB>>>(hb, (unsigned char*)nullptr, batch, n);

    k_head<<<GG, FF>>>(conv_w, conv_b, lin1_w, lin1_b, lin2_w, lin2_b, out);
}

// round 13
// speedup vs baseline: 1.2485x; 1.0685x over previous
#include <cuda_runtime.h>
#include <cuda_fp16.h>
#include <cuda_fp8.h>
#include <math.h>

#define NN 100000
#define EE 1600000
#define EPAD2 1750016         // uint2 records (weighted path): >= EE+NN, even
#define EPAD4 1900064         // uint records (fast path): >= EE+3*NN, mult of 4
#define FF 64
#define GG 512
#define CC 10
#define NB 1024
#define SCALE 16.0f

// ---------------- device scratch (zero-init at load; consumers restore) ----------------
__device__ __align__(128) unsigned char g_x8[(NN + 1) * FF];   // +1 phantom zero row
__device__ __align__(128) unsigned char g_ha[(NN + 1) * FF];
__device__ __align__(128) unsigned char g_hb[(NN + 1) * FF];
__device__ float g_dinv[NN];
__device__ float g_degx[NN];            // zeroed by k_prep after read
__device__ int   g_cnt_e[NN];           // zeroed by k_prep after read
__device__ __align__(8) int2 g_offcnt[NN];
__device__ __align__(8) unsigned short g_rank[EE];
__device__ __align__(16) uint2 g_srt[EPAD2];   // weighted: (w half2, row*4); fast: uint rows
__device__ int   g_total;               // zeroed by k_head
__device__ int   g_wflag;               // zeroed by k_head
__device__ int   g_dhist[NB];           // zeroed by k_scan after read
__device__ int   g_dboff[NB];
__device__ int   g_drank[NN];
__device__ int   g_perm[NN];
__device__ __align__(16) float g_pool[GG * FF]; // zeroed by k_head after read
__device__ int   g_cnt[GG];             // zeroed by k_head after read

__device__ __forceinline__ void red_add_v4(float* addr, float4 v) {
    asm volatile("red.global.add.v4.f32 [%0], {%1, %2, %3, %4};"
                 :: "l"(addr), "f"(v.x), "f"(v.y), "f"(v.z), "f"(v.w)
                 : "memory");
}

__device__ __forceinline__ void fp8x16_to_h2(uint4 u, __half2* h) {
    const __nv_fp8x2_storage_t* p = reinterpret_cast<const __nv_fp8x2_storage_t*>(&u);
#pragma unroll
    for (int k = 0; k < 8; k++) {
        __half2_raw hr = __nv_cvt_fp8x2_to_halfraw2(p[k], __NV_E4M3);
        h[k] = *reinterpret_cast<__half2*>(&hr);
    }
}
__device__ __forceinline__ uint4 f16_to_fp8x16(const float* f) {
    uint4 u;
    __nv_fp8x2_storage_t* p = reinterpret_cast<__nv_fp8x2_storage_t*>(&u);
#pragma unroll
    for (int k = 0; k < 8; k++)
        p[k] = __nv_cvt_float2_to_fp8x2(make_float2(f[2*k], f[2*k+1]), __NV_SATFINITE, __NV_E4M3);
    return u;
}

__device__ __forceinline__ unsigned int pack_w(float w) {
    unsigned short h = __half_as_ushort(__float2half(w));
    return (unsigned int)h | ((unsigned int)h << 16);
}

// ---------------- kernels ----------------

// 4-edge-batched degree/rank (+ wflag)
__global__ void k_deg(const int* __restrict__ col, const float* __restrict__ ew, int e) {
    int t = blockIdx.x * blockDim.x + threadIdx.x;
    int base = t * 4;
    if ((e & 3) == 0) {
        if (base >= e) return;
        int4   c4 = __ldg(reinterpret_cast<const int4*>(col) + t);
        float4 w4 = __ldg(reinterpret_cast<const float4*>(ew) + t);
        ushort4 rk;
        rk.x = (unsigned short)atomicAdd(&g_cnt_e[c4.x], 1);
        rk.y = (unsigned short)atomicAdd(&g_cnt_e[c4.y], 1);
        rk.z = (unsigned short)atomicAdd(&g_cnt_e[c4.z], 1);
        rk.w = (unsigned short)atomicAdd(&g_cnt_e[c4.w], 1);
        if (w4.x != 1.0f) { atomicAdd(&g_degx[c4.x], w4.x - 1.0f); g_wflag = 1; }
        if (w4.y != 1.0f) { atomicAdd(&g_degx[c4.y], w4.y - 1.0f); g_wflag = 1; }
        if (w4.z != 1.0f) { atomicAdd(&g_degx[c4.z], w4.z - 1.0f); g_wflag = 1; }
        if (w4.w != 1.0f) { atomicAdd(&g_degx[c4.w], w4.w - 1.0f); g_wflag = 1; }
        reinterpret_cast<ushort4*>(g_rank)[t] = rk;
    } else {
        for (int m = 0; m < 4; m++) {
            int ei_ = base + m;
            if (ei_ < e) {
                int c = col[ei_];
                g_rank[ei_] = (unsigned short)atomicAdd(&g_cnt_e[c], 1);
                float w = ew[ei_];
                if (w != 1.0f) { atomicAdd(&g_degx[c], w - 1.0f); g_wflag = 1; }
            }
        }
    }
}

// dinv + batch counts + padded offset scan + degree-bucket histogram/rank
__global__ void k_prep(const int* __restrict__ batch, int n) {
    __shared__ int sh[256];
    __shared__ int base;
    __shared__ int lh[NB];
    __shared__ int lb[NB];
    int t = threadIdx.x;
    int i = blockIdx.x * 256 + t;
    int wf = g_wflag;
#pragma unroll
    for (int k = 0; k < NB / 256; k++) lh[t + k * 256] = 0;
    __syncthreads();

    int cnt = 0, cp = 0, db = 0, lrank = 0;
    if (i < n) {
        cnt = g_cnt_e[i];
        float deg = 1.0f + (float)cnt + g_degx[i];
        g_dinv[i] = rsqrtf(deg);
        atomicAdd(&g_cnt[batch[i]], 1);
        g_cnt_e[i] = 0;
        g_degx[i] = 0.0f;
        int nq;
        if (wf) { cp = (cnt + 1) & ~1; nq = cp >> 1; }   // uint2 records
        else    { cp = (cnt + 3) & ~3; nq = cp >> 2; }   // uint records
        db = (nq < NB) ? nq : (NB - 1);
        lrank = atomicAdd(&lh[db], 1);
    }
    __syncthreads();
#pragma unroll
    for (int k = 0; k < NB / 256; k++) {
        int b = t + k * 256;
        if (lh[b] > 0) lb[b] = atomicAdd(&g_dhist[b], lh[b]);
    }
    sh[t] = cp; __syncthreads();
    for (int d = 1; d < 256; d <<= 1) {
        int a = (t >= d) ? sh[t - d] : 0;
        __syncthreads();
        sh[t] += a;
        __syncthreads();
    }
    if (t == 255) base = atomicAdd(&g_total, sh[255]);
    __syncthreads();
    if (i < n) {
        int off = base + sh[t] - cp;
        g_offcnt[i] = make_int2(off, cnt);
        if (wf) {
            for (int z = cnt; z < cp; z++) g_srt[off + z] = make_uint2(0u, 0u);  // w=0
        } else {
            unsigned int* s32 = reinterpret_cast<unsigned int*>(g_srt);
            for (int z = cnt; z < cp; z++) s32[off + z] = (unsigned int)(n * 4); // phantom row
        }
        g_drank[i] = lb[db] + lrank;
    }
}

// warp-shuffle exclusive scan of bucket histogram; restores g_dhist
__global__ void k_scan(void) {
    __shared__ int wsum[32];
    int t = threadIdx.x;
    int lane = t & 31, w = t >> 5;
    int v = g_dhist[t];
    g_dhist[t] = 0;
    int s = v;
#pragma unroll
    for (int d = 1; d < 32; d <<= 1) {
        int a = __shfl_up_sync(0xFFFFFFFF, s, d);
        if (lane >= d) s += a;
    }
    if (lane == 31) wsum[w] = s;
    __syncthreads();
    if (w == 0) {
        int ws = wsum[lane];
#pragma unroll
        for (int d = 1; d < 32; d <<= 1) {
            int a = __shfl_up_sync(0xFFFFFFFF, ws, d);
            if (lane >= d) ws += a;
        }
        wsum[lane] = ws;
    }
    __syncthreads();
    int wbase = (w > 0) ? wsum[w - 1] : 0;
    g_dboff[t] = wbase + s - v;
}

// fused: x -> fp8(dinv*x*SCALE) + perm scatter + 4-edge-batched record scatter
__global__ void k_cvt_scatter(const float* __restrict__ x,
                              const int* __restrict__ row, const int* __restrict__ col,
                              const float* __restrict__ ew, int n, int e) {
    int t = blockIdx.x * blockDim.x + threadIdx.x;
    int wf = g_wflag;
    if (t < n * 4) {
        int i = t >> 2;
        float di = __ldg(&g_dinv[i]) * SCALE;
        const float4* xp = reinterpret_cast<const float4*>(x) + t * 4;
        float f[16];
#pragma unroll
        for (int k = 0; k < 4; k++) {
            float4 v = __ldg(xp + k);
            f[4*k+0] = v.x * di; f[4*k+1] = v.y * di;
            f[4*k+2] = v.z * di; f[4*k+3] = v.w * di;
        }
        reinterpret_cast<uint4*>(g_x8)[t] = f16_to_fp8x16(f);
    }
    if (t < n) {
        int cnt = g_offcnt[t].y;
        int nq = wf ? ((cnt + 1) >> 1) : ((cnt + 3) >> 2);
        int db = (nq < NB) ? nq : (NB - 1);
        g_perm[__ldg(&g_dboff[db]) + g_drank[t]] = t;
    }
    int base = t * 4;
    if ((e & 3) == 0) {
        if (base < e) {
            int4    r4 = __ldg(reinterpret_cast<const int4*>(row) + t);
            int4    c4 = __ldg(reinterpret_cast<const int4*>(col) + t);
            ushort4 rk = reinterpret_cast<const ushort4*>(g_rank)[t];
            int o0 = __ldg(&g_offcnt[c4.x].x);
            int o1 = __ldg(&g_offcnt[c4.y].x);
            int o2 = __ldg(&g_offcnt[c4.z].x);
            int o3 = __ldg(&g_offcnt[c4.w].x);
            if (wf) {
                float4 w4 = __ldg(reinterpret_cast<const float4*>(ew) + t);
                g_srt[o0 + rk.x] = make_uint2(pack_w(w4.x), (unsigned int)(r4.x * 4));
                g_srt[o1 + rk.y] = make_uint2(pack_w(w4.y), (unsigned int)(r4.y * 4));
                g_srt[o2 + rk.z] = make_uint2(pack_w(w4.z), (unsigned int)(r4.z * 4));
                g_srt[o3 + rk.w] = make_uint2(pack_w(w4.w), (unsigned int)(r4.w * 4));
            } else {
                unsigned int* s32 = reinterpret_cast<unsigned int*>(g_srt);
                s32[o0 + rk.x] = (unsigned int)(r4.x * 4);
                s32[o1 + rk.y] = (unsigned int)(r4.y * 4);
                s32[o2 + rk.z] = (unsigned int)(r4.z * 4);
                s32[o3 + rk.w] = (unsigned int)(r4.w * 4);
            }
        }
    } else {
        for (int m = 0; m < 4; m++) {
            int ei_ = base + m;
            if (ei_ < e) {
                int r = row[ei_], c = col[ei_];
                int off = __ldg(&g_offcnt[c].x) + (int)g_rank[ei_];
                if (wf) g_srt[off] = make_uint2(pack_w(ew[ei_]), (unsigned int)(r * 4));
                else    reinterpret_cast<unsigned int*>(g_srt)[off] = (unsigned int)(r * 4);
            }
        }
    }
}

// gather hop over degree-sorted nodes: out = dinv^p * (self + sum w*g[row])
template<bool POOL>
__global__ __launch_bounds__(256, 5)
void k_hop(const unsigned char* __restrict__ hin, unsigned char* __restrict__ hout,
           const int* __restrict__ batch, int n) {
    int t = blockIdx.x * blockDim.x + threadIdx.x;
    int ii = t >> 2, q = t & 3;
    if (ii >= n) return;
    int i = __ldg(&g_perm[ii]);
    const uint4* hin4 = reinterpret_cast<const uint4*>(hin);

    __half2 acc[8];
    fp8x16_to_h2(__ldg(hin4 + i * 4 + q), acc);   // self term (weight 1)

    int2 oc = __ldg(&g_offcnt[i]);
    int wf = g_wflag;

    if (!wf) {
        // fast path: 4B records = row*4; pads point at phantom zero row
        int begq = oc.x >> 2;
        int nq   = (oc.y + 3) >> 2;
        const uint4* srt4 = reinterpret_cast<const uint4*>(g_srt);
        if (nq > 0) {
            uint4 e4 = __ldg(srt4 + begq);
            for (int j = 0; j < nq; j++) {
                uint4 cur = e4;
                if (j + 1 < nq) e4 = __ldg(srt4 + begq + j + 1);
                uint4 hv0 = __ldg(hin4 + (int)cur.x + q);
                uint4 hv1 = __ldg(hin4 + (int)cur.y + q);
                uint4 hv2 = __ldg(hin4 + (int)cur.z + q);
                uint4 hv3 = __ldg(hin4 + (int)cur.w + q);
                __half2 v[8];
                fp8x16_to_h2(hv0, v);
#pragma unroll
                for (int k = 0; k < 8; k++) acc[k] = __hadd2(acc[k], v[k]);
                fp8x16_to_h2(hv1, v);
#pragma unroll
                for (int k = 0; k < 8; k++) acc[k] = __hadd2(acc[k], v[k]);
                fp8x16_to_h2(hv2, v);
#pragma unroll
                for (int k = 0; k < 8; k++) acc[k] = __hadd2(acc[k], v[k]);
                fp8x16_to_h2(hv3, v);
#pragma unroll
                for (int k = 0; k < 8; k++) acc[k] = __hadd2(acc[k], v[k]);
            }
        }
    } else {
        // weighted path: 8B records (w half2, row*4); pads have w=0
        int begq = oc.x >> 1;
        int nq   = (oc.y + 1) >> 1;
        const uint4* srt4 = reinterpret_cast<const uint4*>(g_srt);
        if (nq > 0) {
            uint4 e4 = __ldg(srt4 + begq);
            for (int j = 0; j < nq; j++) {
                uint4 cur = e4;
                if (j + 1 < nq) e4 = __ldg(srt4 + begq + j + 1);
                __half2 w20 = *reinterpret_cast<__half2*>(&cur.x);
                __half2 w21 = *reinterpret_cast<__half2*>(&cur.z);
                uint4 hv0 = __ldg(hin4 + (int)cur.y + q);
                uint4 hv1 = __ldg(hin4 + (int)cur.w + q);
                __half2 v[8];
                fp8x16_to_h2(hv0, v);
#pragma unroll
                for (int k = 0; k < 8; k++) acc[k] = __hfma2(w20, v[k], acc[k]);
                fp8x16_to_h2(hv1, v);
#pragma unroll
                for (int k = 0; k < 8; k++) acc[k] = __hfma2(w21, v[k], acc[k]);
            }
        }
    }

    float s = g_dinv[i];
    float sp = POOL ? s : s * s;
    float o[16];
#pragma unroll
    for (int k = 0; k < 8; k++) {
        float2 af = __half22float2(acc[k]);
        o[2*k]   = af.x * sp;
        o[2*k+1] = af.y * sp;
    }

    if (POOL) {
        int b = __ldg(&batch[i]);
        float* base = g_pool + b * FF + q * 16;
#pragma unroll
        for (int k = 0; k < 4; k++)
            red_add_v4(base + 4*k, make_float4(o[4*k], o[4*k+1], o[4*k+2], o[4*k+3]));
    } else {
        reinterpret_cast<uint4*>(hout)[i * 4 + q] = f16_to_fp8x16(o);
    }
}

// head; restores g_pool/g_cnt/g_total/g_wflag
__global__ void k_head(const float* __restrict__ conv_w, const float* __restrict__ conv_b,
                       const float* __restrict__ lin1_w, const float* __restrict__ lin1_b,
                       const float* __restrict__ lin2_w, const float* __restrict__ lin2_b,
                       float* __restrict__ out) {
    int g = blockIdx.x;
    int f = threadIdx.x;
    __shared__ float sh_t[FF];
    __shared__ float sh_h1[FF];
    __shared__ float sh_h2[FF];
    __shared__ float sh_z[CC];

    float invc = 1.0f / (SCALE * fmaxf((float)g_cnt[g], 1.0f));
    sh_t[f] = g_pool[g * FF + f] * invc;
    __syncthreads();
    g_pool[g * FF + f] = 0.0f;
    if (f == 0) g_cnt[g] = 0;
    if (g == 0 && f == 0) { g_total = 0; g_wflag = 0; }

    float a = conv_b[f];
#pragma unroll
    for (int k = 0; k < FF; k++) a += sh_t[k] * conv_w[k * FF + f];
    sh_h1[f] = a;
    __syncthreads();

    float b = lin1_b[f];
#pragma unroll
    for (int k = 0; k < FF; k++) b += sh_h1[k] * lin1_w[k * FF + f];
    sh_h2[f] = fmaxf(b, 0.0f);
    __syncthreads();

    if (f < CC) {
        float c = lin2_b[f];
#pragma unroll
        for (int k = 0; k < FF; k++) c += sh_h2[k] * lin2_w[k * CC + f];
        sh_z[f] = c;
    }
    __syncthreads();

    if (f < CC) {
        float m = -INFINITY;
#pragma unroll
        for (int j = 0; j < CC; j++) m = fmaxf(m, sh_z[j]);
        float s = 0.0f;
#pragma unroll
        for (int j = 0; j < CC; j++) s += expf(sh_z[j] - m);
        out[g * CC + f] = sh_z[f] - m - logf(s);
    }
}

// ---------------- launch ----------------
extern "C" void kernel_launch(void* const* d_in, const int* in_sizes, int n_in,
                              void* d_out, int out_size) {
    const float* x      = (const float*)d_in[0];
    const int*   ei     = (const int*)d_in[1];
    const float* ew     = (const float*)d_in[2];
    const int*   batch  = (const int*)d_in[3];
    const float* conv_w = (const float*)d_in[4];
    const float* conv_b = (const float*)d_in[5];
    const float* lin1_w = (const float*)d_in[6];
    const float* lin1_b = (const float*)d_in[7];
    const float* lin2_w = (const float*)d_in[8];
    const float* lin2_b = (const float*)d_in[9];
    float* out = (float*)d_out;

    int n = in_sizes[3];
    int e = in_sizes[2];
    const int* row = ei;
    const int* col = ei + e;

    unsigned char *x8, *ha, *hb;
    cudaGetSymbolAddress((void**)&x8, g_x8);
    cudaGetSymbolAddress((void**)&ha, g_ha);
    cudaGetSymbolAddress((void**)&hb, g_hb);

    const int TB = 256;
    int grid_n  = (n + TB - 1) / TB;
    int e4      = (e + 3) / 4;
    int grid_d  = (e4 + TB - 1) / TB;
    int cs_thr  = (n * 4 > e4) ? n * 4 : e4;
    int grid_cs = (cs_thr + TB - 1) / TB;
    int grid_n4 = (n * 4 + TB - 1) / TB;

    k_deg<<<grid_d, TB>>>(col, ew, e);
    k_prep<<<grid_n, TB>>>(batch, n);
    k_scan<<<1, NB>>>();
    k_cvt_scatter<<<grid_cs, TB>>>(x, row, col, ew, n, e);

    k_hop<false><<<grid_n4, TB>>>(x8, ha, batch, n);
    k_hop<false><<<grid_n4, TB>>>(ha, hb, batch, n);
    k_hop<true ><<<grid_n4, TB>>>(hb, (unsigned char*)nullptr, batch, n);

    k_head<<<GG, FF>>>(conv_w, conv_b, lin1_w, lin1_b, lin2_w, lin2_b, out);
}

// round 14
// speedup vs baseline: 1.2489x; 1.0003x over previous
#include <cuda_runtime.h>
#include <cuda_fp16.h>
#include <cuda_fp8.h>
#include <math.h>

#define NN 100000
#define EE 1600000
#define EPAD2 1750016         // uint2 records (weighted path): >= EE+NN, even
#define EPAD4 1900064         // uint records (fast path): >= EE+3*NN, mult of 4
#define FF 64
#define GG 512
#define CC 10
#define NB 1024
#define SCALE 16.0f

// ---------------- device scratch (zero-init at load; consumers restore) ----------------
__device__ __align__(128) unsigned char g_x8[(NN + 1) * FF];   // +1 phantom zero row
__device__ __align__(128) unsigned char g_ha[(NN + 1) * FF];
__device__ __align__(128) unsigned char g_hb[(NN + 1) * FF];
__device__ float g_dinv[NN];
__device__ float g_degx[NN];            // zeroed by k_prep after read
__device__ int   g_cnt_e[NN];           // zeroed by k_prep after read
__device__ __align__(8) int2 g_offcnt[NN];
__device__ __align__(8) unsigned short g_rank[EE];
__device__ __align__(16) uint2 g_srt[EPAD2];   // weighted: (w half2, row*4); fast: uint rows
__device__ int   g_total;               // zeroed by k_head
__device__ int   g_wflag;               // zeroed by k_head
__device__ int   g_dhist[NB];           // zeroed by k_scan after read
__device__ int   g_dboff[NB];
__device__ int   g_drank[NN];
__device__ int   g_perm[NN];
__device__ __align__(16) float g_pool[GG * FF]; // zeroed by k_head after read
__device__ int   g_cnt[GG];             // zeroed by k_head after read

__device__ __forceinline__ void red_add_v4(float* addr, float4 v) {
    asm volatile("red.global.add.v4.f32 [%0], {%1, %2, %3, %4};"
                 :: "l"(addr), "f"(v.x), "f"(v.y), "f"(v.z), "f"(v.w)
                 : "memory");
}

__device__ __forceinline__ void fp8x16_to_h2(uint4 u, __half2* h) {
    const __nv_fp8x2_storage_t* p = reinterpret_cast<const __nv_fp8x2_storage_t*>(&u);
#pragma unroll
    for (int k = 0; k < 8; k++) {
        __half2_raw hr = __nv_cvt_fp8x2_to_halfraw2(p[k], __NV_E4M3);
        h[k] = *reinterpret_cast<__half2*>(&hr);
    }
}
__device__ __forceinline__ uint4 f16_to_fp8x16(const float* f) {
    uint4 u;
    __nv_fp8x2_storage_t* p = reinterpret_cast<__nv_fp8x2_storage_t*>(&u);
#pragma unroll
    for (int k = 0; k < 8; k++)
        p[k] = __nv_cvt_float2_to_fp8x2(make_float2(f[2*k], f[2*k+1]), __NV_SATFINITE, __NV_E4M3);
    return u;
}

__device__ __forceinline__ unsigned int pack_w(float w) {
    unsigned short h = __half_as_ushort(__float2half(w));
    return (unsigned int)h | ((unsigned int)h << 16);
}

// ---------------- kernels ----------------

// 4-edge-batched degree/rank (+ wflag)
__global__ void k_deg(const int* __restrict__ col, const float* __restrict__ ew, int e) {
    int t = blockIdx.x * blockDim.x + threadIdx.x;
    int base = t * 4;
    if ((e & 3) == 0) {
        if (base >= e) return;
        int4   c4 = __ldg(reinterpret_cast<const int4*>(col) + t);
        float4 w4 = __ldg(reinterpret_cast<const float4*>(ew) + t);
        ushort4 rk;
        rk.x = (unsigned short)atomicAdd(&g_cnt_e[c4.x], 1);
        rk.y = (unsigned short)atomicAdd(&g_cnt_e[c4.y], 1);
        rk.z = (unsigned short)atomicAdd(&g_cnt_e[c4.z], 1);
        rk.w = (unsigned short)atomicAdd(&g_cnt_e[c4.w], 1);
        if (w4.x != 1.0f) { atomicAdd(&g_degx[c4.x], w4.x - 1.0f); g_wflag = 1; }
        if (w4.y != 1.0f) { atomicAdd(&g_degx[c4.y], w4.y - 1.0f); g_wflag = 1; }
        if (w4.z != 1.0f) { atomicAdd(&g_degx[c4.z], w4.z - 1.0f); g_wflag = 1; }
        if (w4.w != 1.0f) { atomicAdd(&g_degx[c4.w], w4.w - 1.0f); g_wflag = 1; }
        reinterpret_cast<ushort4*>(g_rank)[t] = rk;
    } else {
        for (int m = 0; m < 4; m++) {
            int ei_ = base + m;
            if (ei_ < e) {
                int c = col[ei_];
                g_rank[ei_] = (unsigned short)atomicAdd(&g_cnt_e[c], 1);
                float w = ew[ei_];
                if (w != 1.0f) { atomicAdd(&g_degx[c], w - 1.0f); g_wflag = 1; }
            }
        }
    }
}

// dinv + batch counts + padded offset scan + degree-bucket histogram/rank
__global__ void k_prep(const int* __restrict__ batch, int n) {
    __shared__ int sh[256];
    __shared__ int base;
    __shared__ int lh[NB];
    __shared__ int lb[NB];
    int t = threadIdx.x;
    int i = blockIdx.x * 256 + t;
    int wf = g_wflag;
#pragma unroll
    for (int k = 0; k < NB / 256; k++) lh[t + k * 256] = 0;
    __syncthreads();

    int cnt = 0, cp = 0, db = 0, lrank = 0;
    if (i < n) {
        cnt = g_cnt_e[i];
        float deg = 1.0f + (float)cnt + g_degx[i];
        g_dinv[i] = rsqrtf(deg);
        atomicAdd(&g_cnt[batch[i]], 1);
        g_cnt_e[i] = 0;
        g_degx[i] = 0.0f;
        int nq;
        if (wf) { cp = (cnt + 1) & ~1; nq = cp >> 1; }   // uint2 records
        else    { cp = (cnt + 3) & ~3; nq = cp >> 2; }   // uint records
        db = (nq < NB) ? nq : (NB - 1);
        lrank = atomicAdd(&lh[db], 1);
    }
    __syncthreads();
#pragma unroll
    for (int k = 0; k < NB / 256; k++) {
        int b = t + k * 256;
        if (lh[b] > 0) lb[b] = atomicAdd(&g_dhist[b], lh[b]);
    }
    sh[t] = cp; __syncthreads();
    for (int d = 1; d < 256; d <<= 1) {
        int a = (t >= d) ? sh[t - d] : 0;
        __syncthreads();
        sh[t] += a;
        __syncthreads();
    }
    if (t == 255) base = atomicAdd(&g_total, sh[255]);
    __syncthreads();
    if (i < n) {
        int off = base + sh[t] - cp;
        g_offcnt[i] = make_int2(off, cnt);
        if (wf) {
            for (int z = cnt; z < cp; z++) g_srt[off + z] = make_uint2(0u, 0u);  // w=0
        } else {
            unsigned int* s32 = reinterpret_cast<unsigned int*>(g_srt);
            for (int z = cnt; z < cp; z++) s32[off + z] = (unsigned int)(n * 4); // phantom row
        }
        g_drank[i] = lb[db] + lrank;
    }
}

// warp-shuffle exclusive scan of bucket histogram; restores g_dhist
__global__ void k_scan(void) {
    __shared__ int wsum[32];
    int t = threadIdx.x;
    int lane = t & 31, w = t >> 5;
    int v = g_dhist[t];
    g_dhist[t] = 0;
    int s = v;
#pragma unroll
    for (int d = 1; d < 32; d <<= 1) {
        int a = __shfl_up_sync(0xFFFFFFFF, s, d);
        if (lane >= d) s += a;
    }
    if (lane == 31) wsum[w] = s;
    __syncthreads();
    if (w == 0) {
        int ws = wsum[lane];
#pragma unroll
        for (int d = 1; d < 32; d <<= 1) {
            int a = __shfl_up_sync(0xFFFFFFFF, ws, d);
            if (lane >= d) ws += a;
        }
        wsum[lane] = ws;
    }
    __syncthreads();
    int wbase = (w > 0) ? wsum[w - 1] : 0;
    g_dboff[t] = wbase + s - v;
}

// fused: x -> fp8(dinv*x*SCALE) + perm scatter + 4-edge-batched record scatter
__global__ void k_cvt_scatter(const float* __restrict__ x,
                              const int* __restrict__ row, const int* __restrict__ col,
                              const float* __restrict__ ew, int n, int e) {
    int t = blockIdx.x * blockDim.x + threadIdx.x;
    int wf = g_wflag;
    if (t < n * 4) {
        int i = t >> 2;
        float di = __ldg(&g_dinv[i]) * SCALE;
        const float4* xp = reinterpret_cast<const float4*>(x) + t * 4;
        float f[16];
#pragma unroll
        for (int k = 0; k < 4; k++) {
            float4 v = __ldg(xp + k);
            f[4*k+0] = v.x * di; f[4*k+1] = v.y * di;
            f[4*k+2] = v.z * di; f[4*k+3] = v.w * di;
        }
        reinterpret_cast<uint4*>(g_x8)[t] = f16_to_fp8x16(f);
    }
    if (t < n) {
        int cnt = g_offcnt[t].y;
        int nq = wf ? ((cnt + 1) >> 1) : ((cnt + 3) >> 2);
        int db = (nq < NB) ? nq : (NB - 1);
        g_perm[__ldg(&g_dboff[db]) + g_drank[t]] = t;
    }
    int base = t * 4;
    if ((e & 3) == 0) {
        if (base < e) {
            int4    r4 = __ldg(reinterpret_cast<const int4*>(row) + t);
            int4    c4 = __ldg(reinterpret_cast<const int4*>(col) + t);
            ushort4 rk = reinterpret_cast<const ushort4*>(g_rank)[t];
            int o0 = __ldg(&g_offcnt[c4.x].x);
            int o1 = __ldg(&g_offcnt[c4.y].x);
            int o2 = __ldg(&g_offcnt[c4.z].x);
            int o3 = __ldg(&g_offcnt[c4.w].x);
            if (wf) {
                float4 w4 = __ldg(reinterpret_cast<const float4*>(ew) + t);
                g_srt[o0 + rk.x] = make_uint2(pack_w(w4.x), (unsigned int)(r4.x * 4));
                g_srt[o1 + rk.y] = make_uint2(pack_w(w4.y), (unsigned int)(r4.y * 4));
                g_srt[o2 + rk.z] = make_uint2(pack_w(w4.z), (unsigned int)(r4.z * 4));
                g_srt[o3 + rk.w] = make_uint2(pack_w(w4.w), (unsigned int)(r4.w * 4));
            } else {
                unsigned int* s32 = reinterpret_cast<unsigned int*>(g_srt);
                s32[o0 + rk.x] = (unsigned int)(r4.x * 4);
                s32[o1 + rk.y] = (unsigned int)(r4.y * 4);
                s32[o2 + rk.z] = (unsigned int)(r4.z * 4);
                s32[o3 + rk.w] = (unsigned int)(r4.w * 4);
            }
        }
    } else {
        for (int m = 0; m < 4; m++) {
            int ei_ = base + m;
            if (ei_ < e) {
                int r = row[ei_], c = col[ei_];
                int off = __ldg(&g_offcnt[c].x) + (int)g_rank[ei_];
                if (wf) g_srt[off] = make_uint2(pack_w(ew[ei_]), (unsigned int)(r * 4));
                else    reinterpret_cast<unsigned int*>(g_srt)[off] = (unsigned int)(r * 4);
            }
        }
    }
}

// gather hop over degree-sorted nodes: out = dinv^p * (self + sum w*g[row])
template<bool POOL>
__global__ __launch_bounds__(256, 5)
void k_hop(const unsigned char* __restrict__ hin, unsigned char* __restrict__ hout,
           const int* __restrict__ batch, int n) {
    int t = blockIdx.x * blockDim.x + threadIdx.x;
    int ii = t >> 2, q = t & 3;
    if (ii >= n) return;
    int i = __ldg(&g_perm[ii]);
    const uint4* hin4 = reinterpret_cast<const uint4*>(hin);

    __half2 acc[8];
    fp8x16_to_h2(__ldg(hin4 + i * 4 + q), acc);   // self term (weight 1)

    int2 oc = __ldg(&g_offcnt[i]);
    int wf = g_wflag;

    if (!wf) {
        // fast path: 4B records = row*4; pads point at phantom zero row
        int begq = oc.x >> 2;
        int nq   = (oc.y + 3) >> 2;
        const uint4* srt4 = reinterpret_cast<const uint4*>(g_srt);
        if (nq > 0) {
            uint4 e4 = __ldg(srt4 + begq);
            for (int j = 0; j < nq; j++) {
                uint4 cur = e4;
                if (j + 1 < nq) e4 = __ldg(srt4 + begq + j + 1);
                uint4 hv0 = __ldg(hin4 + (int)cur.x + q);
                uint4 hv1 = __ldg(hin4 + (int)cur.y + q);
                uint4 hv2 = __ldg(hin4 + (int)cur.z + q);
                uint4 hv3 = __ldg(hin4 + (int)cur.w + q);
                __half2 v[8];
                fp8x16_to_h2(hv0, v);
#pragma unroll
                for (int k = 0; k < 8; k++) acc[k] = __hadd2(acc[k], v[k]);
                fp8x16_to_h2(hv1, v);
#pragma unroll
                for (int k = 0; k < 8; k++) acc[k] = __hadd2(acc[k], v[k]);
                fp8x16_to_h2(hv2, v);
#pragma unroll
                for (int k = 0; k < 8; k++) acc[k] = __hadd2(acc[k], v[k]);
                fp8x16_to_h2(hv3, v);
#pragma unroll
                for (int k = 0; k < 8; k++) acc[k] = __hadd2(acc[k], v[k]);
            }
        }
    } else {
        // weighted path: 8B records (w half2, row*4); pads have w=0
        int begq = oc.x >> 1;
        int nq   = (oc.y + 1) >> 1;
        const uint4* srt4 = reinterpret_cast<const uint4*>(g_srt);
        if (nq > 0) {
            uint4 e4 = __ldg(srt4 + begq);
            for (int j = 0; j < nq; j++) {
                uint4 cur = e4;
                if (j + 1 < nq) e4 = __ldg(srt4 + begq + j + 1);
                __half2 w20 = *reinterpret_cast<__half2*>(&cur.x);
                __half2 w21 = *reinterpret_cast<__half2*>(&cur.z);
                uint4 hv0 = __ldg(hin4 + (int)cur.y + q);
                uint4 hv1 = __ldg(hin4 + (int)cur.w + q);
                __half2 v[8];
                fp8x16_to_h2(hv0, v);
#pragma unroll
                for (int k = 0; k < 8; k++) acc[k] = __hfma2(w20, v[k], acc[k]);
                fp8x16_to_h2(hv1, v);
#pragma unroll
                for (int k = 0; k < 8; k++) acc[k] = __hfma2(w21, v[k], acc[k]);
            }
        }
    }

    float s = g_dinv[i];
    float sp = POOL ? s : s * s;
    float o[16];
#pragma unroll
    for (int k = 0; k < 8; k++) {
        float2 af = __half22float2(acc[k]);
        o[2*k]   = af.x * sp;
        o[2*k+1] = af.y * sp;
    }

    if (POOL) {
        int b = __ldg(&batch[i]);
        float* base = g_pool + b * FF + q * 16;
#pragma unroll
        for (int k = 0; k < 4; k++)
            red_add_v4(base + 4*k, make_float4(o[4*k], o[4*k+1], o[4*k+2], o[4*k+3]));
    } else {
        reinterpret_cast<uint4*>(hout)[i * 4 + q] = f16_to_fp8x16(o);
    }
}

// head; restores g_pool/g_cnt/g_total/g_wflag
__global__ void k_head(const float* __restrict__ conv_w, const float* __restrict__ conv_b,
                       const float* __restrict__ lin1_w, const float* __restrict__ lin1_b,
                       const float* __restrict__ lin2_w, const float* __restrict__ lin2_b,
                       float* __restrict__ out) {
    int g = blockIdx.x;
    int f = threadIdx.x;
    __shared__ float sh_t[FF];
    __shared__ float sh_h1[FF];
    __shared__ float sh_h2[FF];
    __shared__ float sh_z[CC];

    float invc = 1.0f / (SCALE * fmaxf((float)g_cnt[g], 1.0f));
    sh_t[f] = g_pool[g * FF + f] * invc;
    __syncthreads();
    g_pool[g * FF + f] = 0.0f;
    if (f == 0) g_cnt[g] = 0;
    if (g == 0 && f == 0) { g_total = 0; g_wflag = 0; }

    float a = conv_b[f];
#pragma unroll
    for (int k = 0; k < FF; k++) a += sh_t[k] * conv_w[k * FF + f];
    sh_h1[f] = a;
    __syncthreads();

    float b = lin1_b[f];
#pragma unroll
    for (int k = 0; k < FF; k++) b += sh_h1[k] * lin1_w[k * FF + f];
    sh_h2[f] = fmaxf(b, 0.0f);
    __syncthreads();

    if (f < CC) {
        float c = lin2_b[f];
#pragma unroll
        for (int k = 0; k < FF; k++) c += sh_h2[k] * lin2_w[k * CC + f];
        sh_z[f] = c;
    }
    __syncthreads();

    if (f < CC) {
        float m = -INFINITY;
#pragma unroll
        for (int j = 0; j < CC; j++) m = fmaxf(m, sh_z[j]);
        float s = 0.0f;
#pragma unroll
        for (int j = 0; j < CC; j++) s += expf(sh_z[j] - m);
        out[g * CC + f] = sh_z[f] - m - logf(s);
    }
}

// ---------------- launch ----------------
extern "C" void kernel_launch(void* const* d_in, const int* in_sizes, int n_in,
                              void* d_out, int out_size) {
    const float* x      = (const float*)d_in[0];
    const int*   ei     = (const int*)d_in[1];
    const float* ew     = (const float*)d_in[2];
    const int*   batch  = (const int*)d_in[3];
    const float* conv_w = (const float*)d_in[4];
    const float* conv_b = (const float*)d_in[5];
    const float* lin1_w = (const float*)d_in[6];
    const float* lin1_b = (const float*)d_in[7];
    const float* lin2_w = (const float*)d_in[8];
    const float* lin2_b = (const float*)d_in[9];
    float* out = (float*)d_out;

    int n = in_sizes[3];
    int e = in_sizes[2];
    const int* row = ei;
    const int* col = ei + e;

    unsigned char *x8, *ha, *hb;
    cudaGetSymbolAddress((void**)&x8, g_x8);
    cudaGetSymbolAddress((void**)&ha, g_ha);
    cudaGetSymbolAddress((void**)&hb, g_hb);

    const int TB = 256;
    int grid_n  = (n + TB - 1) / TB;
    int e4      = (e + 3) / 4;
    int grid_d  = (e4 + TB - 1) / TB;
    int cs_thr  = (n * 4 > e4) ? n * 4 : e4;
    int grid_cs = (cs_thr + TB - 1) / TB;
    int grid_n4 = (n * 4 + TB - 1) / TB;

    k_deg<<<grid_d, TB>>>(col, ew, e);
    k_prep<<<grid_n, TB>>>(batch, n);
    k_scan<<<1, NB>>>();
    k_cvt_scatter<<<grid_cs, TB>>>(x, row, col, ew, n, e);

    k_hop<false><<<grid_n4, TB>>>(x8, ha, batch, n);
    k_hop<false><<<grid_n4, TB>>>(ha, hb, batch, n);
    k_hop<true ><<<grid_n4, TB>>>(hb, (unsigned char*)nullptr, batch, n);

    k_head<<<GG, FF>>>(conv_w, conv_b, lin1_w, lin1_b, lin2_w, lin2_b, out);
}